// round 7
// baseline (speedup 1.0000x reference)
#include <cuda_runtime.h>
#include <cuda_fp16.h>
#include <cstdint>
#include <cstddef>

// Problem constants
#define BV 4
#define HN 16
#define SV 1024
#define DV 64
#define BH (BV*HN)

// fp16 operands (device scratch; no allocation)
__device__ __half g_qhi[(size_t)BH * SV * DV];
__device__ __half g_khi[(size_t)BH * SV * DV];

__device__ __forceinline__ uint32_t smem_u32(const void* p) {
    uint32_t a;
    asm("{ .reg .u64 t; cvta.to.shared.u64 t, %1; cvt.u32.u64 %0, t; }" : "=r"(a) : "l"(p));
    return a;
}
__device__ __forceinline__ uint32_t sw128(uint32_t off) {
    return off ^ ((off >> 3) & 0x70);
}
__device__ __forceinline__ void ldsm_x4(uint32_t addr, uint32_t& r0, uint32_t& r1,
                                        uint32_t& r2, uint32_t& r3) {
    asm volatile("ldmatrix.sync.aligned.m8n8.x4.shared.b16 {%0,%1,%2,%3}, [%4];"
                 : "=r"(r0), "=r"(r1), "=r"(r2), "=r"(r3) : "r"(addr));
}
__device__ __forceinline__ void mma_f16(float* c, const uint32_t* a,
                                        uint32_t b0, uint32_t b1) {
    asm volatile(
        "mma.sync.aligned.m16n8k16.row.col.f32.f16.f16.f32 "
        "{%0,%1,%2,%3}, {%4,%5,%6,%7}, {%8,%9}, {%0,%1,%2,%3};"
        : "+f"(c[0]), "+f"(c[1]), "+f"(c[2]), "+f"(c[3])
        : "r"(a[0]), "r"(a[1]), "r"(a[2]), "r"(a[3]), "r"(b0), "r"(b1));
}

// ---------------------------------------------------------------------------
// Kernel 1 (fused prep grid): unchanged from R6 (≈15us)
//  y <  BH : fold via tensor cores: q'' = q @ M_h,  M_h = 32*I + Wd[h]*W[h]
//  y >= BH : convert k -> fp16 (g_khi)
// ---------------------------------------------------------------------------
#define PREP_SMEM (49152 + 1024)
__global__ __launch_bounds__(256, 2)
void prep_kernel(const float* __restrict__ q,
                 const float* __restrict__ k,
                 const float* __restrict__ W,
                 const float* __restrict__ Wd)
{
    const int t = threadIdx.x;

    if (blockIdx.y >= BH) {
        const int pb = (blockIdx.y - BH) * gridDim.x + blockIdx.x;   // 0..127
        const size_t base = (size_t)pb * 8192;
        __half2* ph = reinterpret_cast<__half2*>(g_khi);
        #pragma unroll
        for (int it = 0; it < 32; it++) {
            const size_t i = base + (size_t)it * 256 + t;
            float4 v = reinterpret_cast<const float4*>(k)[i];
            ph[2 * i]     = __floats2half2_rn(v.x, v.y);
            ph[2 * i + 1] = __floats2half2_rn(v.z, v.w);
        }
        return;
    }

    extern __shared__ char smem_raw[];
    const uint32_t smem_base = smem_u32(smem_raw);
    const uint32_t base_al   = (smem_base + 1023u) & ~1023u;
    char* tilec = smem_raw + (base_al - smem_base);
    const uint32_t Ah = base_al;
    const uint32_t Al = base_al + 16384;
    const uint32_t Mh = base_al + 32768;
    const uint32_t Ml = base_al + 40960;

    const int bh = blockIdx.y;
    const int h  = bh % HN;
    const int i0 = blockIdx.x * 128;

    const float* qb = q + (size_t)bh * SV * DV + (size_t)i0 * DV;
    const float* Wh = W + (size_t)h * DV * DV;
    const float  wd = Wd[h];

    #pragma unroll
    for (int it = 0; it < 16; it++) {
        const int idx = t + it * 256;
        const int d = idx >> 6, e = idx & 63;
        float val = wd * Wh[idx] + (d == e ? 32.0f : 0.0f);
        __half hi = __float2half(val);
        __half lo = __float2half(val - __half2float(hi));
        const uint32_t off = sw128((uint32_t)(e * 128 + d * 2));
        *reinterpret_cast<__half*>(tilec + (Mh - base_al) + off) = hi;
        *reinterpret_cast<__half*>(tilec + (Ml - base_al) + off) = lo;
    }

    #pragma unroll
    for (int it = 0; it < 4; it++) {
        const int idx = t + it * 256;
        const int row = idx >> 3;
        const int c8  = idx & 7;
        const float4 v0 = reinterpret_cast<const float4*>(qb + (size_t)row * DV)[c8 * 2];
        const float4 v1 = reinterpret_cast<const float4*>(qb + (size_t)row * DV)[c8 * 2 + 1];
        __half h0 = __float2half(v0.x), h1 = __float2half(v0.y);
        __half h2 = __float2half(v0.z), h3 = __float2half(v0.w);
        __half h4 = __float2half(v1.x), h5 = __float2half(v1.y);
        __half h6 = __float2half(v1.z), h7 = __float2half(v1.w);
        __half2 hv[4] = { __half2(h0,h1), __half2(h2,h3), __half2(h4,h5), __half2(h6,h7) };
        __half2 lv[4] = {
            __floats2half2_rn(v0.x - __half2float(h0), v0.y - __half2float(h1)),
            __floats2half2_rn(v0.z - __half2float(h2), v0.w - __half2float(h3)),
            __floats2half2_rn(v1.x - __half2float(h4), v1.y - __half2float(h5)),
            __floats2half2_rn(v1.z - __half2float(h6), v1.w - __half2float(h7)) };
        const uint32_t off = sw128((uint32_t)(row * 128 + c8 * 16));
        *reinterpret_cast<uint4*>(tilec + off)         = *reinterpret_cast<uint4*>(hv);
        *reinterpret_cast<uint4*>(tilec + 16384 + off) = *reinterpret_cast<uint4*>(lv);
    }
    __syncthreads();

    const int wid  = t >> 5;
    const int lane = t & 31;
    const int m0w  = (wid & 3) * 32;
    const int n0w  = (wid >> 2) * 32;

    float acc[2][4][4];
    #pragma unroll
    for (int m = 0; m < 2; m++)
        #pragma unroll
        for (int n = 0; n < 4; n++)
            #pragma unroll
            for (int r = 0; r < 4; r++) acc[m][n][r] = 0.0f;

    const uint32_t a_row = lane & 15;
    const uint32_t a_ch  = (lane >> 4) << 4;
    const uint32_t b_row = (lane & 7) | ((lane >> 4) << 3);
    const uint32_t b_ch  = ((lane >> 3) & 1) << 4;

    #pragma unroll
    for (int kk = 0; kk < 4; kk++) {
        const uint32_t kb = (uint32_t)kk * 32;
        uint32_t ah[2][4], al[2][4];
        #pragma unroll
        for (int m = 0; m < 2; m++) {
            const uint32_t ro = sw128((uint32_t)(m0w + m * 16 + a_row) * 128 + kb + a_ch);
            ldsm_x4(Ah + ro, ah[m][0], ah[m][1], ah[m][2], ah[m][3]);
            ldsm_x4(Al + ro, al[m][0], al[m][1], al[m][2], al[m][3]);
        }
        uint32_t bh_f[4][2], bl_f[4][2];
        #pragma unroll
        for (int tn = 0; tn < 2; tn++) {
            const uint32_t ro = sw128((uint32_t)(n0w + tn * 16 + b_row) * 128 + kb + b_ch);
            ldsm_x4(Mh + ro, bh_f[2*tn][0], bh_f[2*tn][1], bh_f[2*tn+1][0], bh_f[2*tn+1][1]);
            ldsm_x4(Ml + ro, bl_f[2*tn][0], bl_f[2*tn][1], bl_f[2*tn+1][0], bl_f[2*tn+1][1]);
        }
        #pragma unroll
        for (int m = 0; m < 2; m++)
            #pragma unroll
            for (int n = 0; n < 4; n++) {
                mma_f16(acc[m][n], ah[m], bh_f[n][0], bh_f[n][1]);
                mma_f16(acc[m][n], ah[m], bl_f[n][0], bl_f[n][1]);
                mma_f16(acc[m][n], al[m], bh_f[n][0], bh_f[n][1]);
            }
    }

    __half* oh = g_qhi + (size_t)bh * SV * DV;
    #pragma unroll
    for (int m = 0; m < 2; m++) {
        #pragma unroll
        for (int half = 0; half < 2; half++) {
            const int row = i0 + m0w + m * 16 + half * 8 + (lane >> 2);
            #pragma unroll
            for (int n = 0; n < 4; n++) {
                const int col = n0w + n * 8 + (lane & 3) * 2;
                __half2 v = __floats2half2_rn(acc[m][n][half * 2], acc[m][n][half * 2 + 1]);
                *reinterpret_cast<__half2*>(oh + (size_t)row * DV + col) = v;
            }
        }
    }
}

// ---------------------------------------------------------------------------
// Kernel 2: batched GEMM on HMMA, single pass fp16 -> f32.
//   out[bh][i][j] = q''_i · k_j + Wd[h]*b[h]
// 128x128 tile per CTA, grid (8,8,64) = 4096, 256 threads, warp tile 32x64.
// Epilogue: acc -> padded smem staging -> fully coalesced STG.128.
// ---------------------------------------------------------------------------
#define TILE_B 16384
#define ST_STRIDE 132                           // floats per staged row (+4 pad)
#define ST_BYTES  (128 * ST_STRIDE * 4)         // 67584
#define SC_SMEM   (2 * TILE_B + ST_BYTES + 1024)

__global__ __launch_bounds__(256, 2)
void score_mma_kernel(const float* __restrict__ b,
                      const float* __restrict__ Wd,
                      float* __restrict__ out)
{
    extern __shared__ char smem_raw[];
    const uint32_t smem_base = smem_u32(smem_raw);
    const uint32_t base_al   = (smem_base + 1023u) & ~1023u;
    char* tilec = smem_raw + (base_al - smem_base);
    const uint32_t Ab = base_al;
    const uint32_t Bb = base_al + TILE_B;
    float* stg = reinterpret_cast<float*>(tilec + 2 * TILE_B);

    const int t    = threadIdx.x;
    const int wid  = t >> 5;
    const int lane = t & 31;
    const int bh   = blockIdx.z;
    const int h    = bh % HN;
    const int i0   = blockIdx.y * 128;
    const int j0   = blockIdx.x * 128;

    // ---- Load A (q'') and B (k) tiles into swizzled smem ----
    const size_t boff = (size_t)bh * SV * DV;
    const __half* qh = g_qhi + boff + (size_t)i0 * DV;
    const __half* kh = g_khi + boff + (size_t)j0 * DV;

    #pragma unroll
    for (int it = 0; it < 4; it++) {
        const int idx = t + it * 256;      // 0..1023
        const int row = idx >> 3;
        const int c16 = idx & 7;
        const uint32_t off = sw128((uint32_t)(row * 128 + c16 * 16));
        *reinterpret_cast<uint4*>(tilec + off) =
            reinterpret_cast<const uint4*>(qh + (size_t)row * DV)[c16];
        *reinterpret_cast<uint4*>(tilec + TILE_B + off) =
            reinterpret_cast<const uint4*>(kh + (size_t)row * DV)[c16];
    }
    __syncthreads();

    // ---- Per-warp MMA: warp (mw, nw) owns rows mw*32..+31, cols nw*64..+63 ----
    const int m0w = (wid & 3) * 32;
    const int n0w = (wid >> 2) * 64;

    float acc[2][8][4];
    #pragma unroll
    for (int m = 0; m < 2; m++)
        #pragma unroll
        for (int n = 0; n < 8; n++)
            #pragma unroll
            for (int r = 0; r < 4; r++) acc[m][n][r] = 0.0f;

    const uint32_t a_row = lane & 15;
    const uint32_t a_ch  = (lane >> 4) << 4;
    const uint32_t b_row = (lane & 7) | ((lane >> 4) << 3);
    const uint32_t b_ch  = ((lane >> 3) & 1) << 4;

    #pragma unroll
    for (int kk = 0; kk < 4; kk++) {
        const uint32_t kb = (uint32_t)kk * 32;
        uint32_t a[2][4];
        #pragma unroll
        for (int m = 0; m < 2; m++) {
            const uint32_t ro = sw128((uint32_t)(m0w + m * 16 + a_row) * 128 + kb + a_ch);
            ldsm_x4(Ab + ro, a[m][0], a[m][1], a[m][2], a[m][3]);
        }
        uint32_t bf[8][2];
        #pragma unroll
        for (int tn = 0; tn < 4; tn++) {
            const uint32_t ro = sw128((uint32_t)(n0w + tn * 16 + b_row) * 128 + kb + b_ch);
            ldsm_x4(Bb + ro, bf[2*tn][0], bf[2*tn][1], bf[2*tn+1][0], bf[2*tn+1][1]);
        }
        #pragma unroll
        for (int m = 0; m < 2; m++)
            #pragma unroll
            for (int n = 0; n < 8; n++)
                mma_f16(acc[m][n], a[m], bf[n][0], bf[n][1]);
    }

    // ---- Epilogue stage 1: acc (+bias) -> padded smem staging (STS.64) ----
    const float cbias = Wd[h] * b[h];
    #pragma unroll
    for (int m = 0; m < 2; m++) {
        #pragma unroll
        for (int half = 0; half < 2; half++) {
            const int row = m0w + m * 16 + half * 8 + (lane >> 2);
            float* prow = stg + (size_t)row * ST_STRIDE + n0w + (lane & 3) * 2;
            #pragma unroll
            for (int n = 0; n < 8; n++) {
                float2 v;
                v.x = acc[m][n][half * 2 + 0] + cbias;
                v.y = acc[m][n][half * 2 + 1] + cbias;
                *reinterpret_cast<float2*>(prow + n * 8) = v;
            }
        }
    }
    __syncthreads();

    // ---- Epilogue stage 2: coalesced STG.128; each warp writes one full
    //      512B output row segment per iteration (4 full 128B wavefronts) ----
    float* ob = out + (size_t)bh * SV * SV + (size_t)i0 * SV + j0;
    #pragma unroll
    for (int it = 0; it < 16; it++) {
        const int row = it * 8 + wid;
        float4 v = *reinterpret_cast<const float4*>(stg + (size_t)row * ST_STRIDE + lane * 4);
        *reinterpret_cast<float4*>(ob + (size_t)row * SV + lane * 4) = v;
    }
}

// ---------------------------------------------------------------------------
extern "C" void kernel_launch(void* const* d_in, const int* in_sizes, int n_in,
                              void* d_out, int out_size)
{
    const float* q  = (const float*)d_in[0];
    const float* k  = (const float*)d_in[1];
    const float* W  = (const float*)d_in[2];
    const float* b  = (const float*)d_in[3];
    const float* Wd = (const float*)d_in[4];
    float* out = (float*)d_out;

    cudaFuncSetAttribute(prep_kernel,
                         cudaFuncAttributeMaxDynamicSharedMemorySize, PREP_SMEM);
    cudaFuncSetAttribute(score_mma_kernel,
                         cudaFuncAttributeMaxDynamicSharedMemorySize, SC_SMEM);

    dim3 g1(8, BH + 16);
    prep_kernel<<<g1, 256, PREP_SMEM>>>(q, k, W, Wd);

    dim3 g3(SV / 128, SV / 128, BH);
    score_mma_kernel<<<g3, 256, SC_SMEM>>>(b, Wd, out);
}

// round 8
// speedup vs baseline: 1.2754x; 1.2754x over previous
#include <cuda_runtime.h>
#include <cuda_fp16.h>
#include <cstdint>
#include <cstddef>

// Problem constants
#define BV 4
#define HN 16
#define SV 1024
#define DV 64
#define BH (BV*HN)

// fp16 operands (device scratch; no allocation)
__device__ __half g_qhi[(size_t)BH * SV * DV];
__device__ __half g_khi[(size_t)BH * SV * DV];

__device__ __forceinline__ uint32_t smem_u32(const void* p) {
    uint32_t a;
    asm("{ .reg .u64 t; cvta.to.shared.u64 t, %1; cvt.u32.u64 %0, t; }" : "=r"(a) : "l"(p));
    return a;
}
__device__ __forceinline__ uint32_t sw128(uint32_t off) {
    return off ^ ((off >> 3) & 0x70);
}
__device__ __forceinline__ void ldsm_x4(uint32_t addr, uint32_t& r0, uint32_t& r1,
                                        uint32_t& r2, uint32_t& r3) {
    asm volatile("ldmatrix.sync.aligned.m8n8.x4.shared.b16 {%0,%1,%2,%3}, [%4];"
                 : "=r"(r0), "=r"(r1), "=r"(r2), "=r"(r3) : "r"(addr));
}
__device__ __forceinline__ void mma_f16(float* c, const uint32_t* a,
                                        uint32_t b0, uint32_t b1) {
    asm volatile(
        "mma.sync.aligned.m16n8k16.row.col.f32.f16.f16.f32 "
        "{%0,%1,%2,%3}, {%4,%5,%6,%7}, {%8,%9}, {%0,%1,%2,%3};"
        : "+f"(c[0]), "+f"(c[1]), "+f"(c[2]), "+f"(c[3])
        : "r"(a[0]), "r"(a[1]), "r"(a[2]), "r"(a[3]), "r"(b0), "r"(b1));
}
__device__ __forceinline__ void cp_async16(uint32_t smem_dst, const void* gsrc) {
    asm volatile("cp.async.cg.shared.global [%0], [%1], 16;"
                 :: "r"(smem_dst), "l"(gsrc));
}
#define CP_COMMIT() asm volatile("cp.async.commit_group;" ::: "memory")
#define CP_WAIT0()  asm volatile("cp.async.wait_group 0;"  ::: "memory")

// ---------------------------------------------------------------------------
// Kernel 1 (fused prep grid): unchanged from R6 (≈15us)
//  y <  BH : fold via tensor cores: q'' = q @ M_h,  M_h = 32*I + Wd[h]*W[h]
//  y >= BH : convert k -> fp16 (g_khi)
// ---------------------------------------------------------------------------
#define PREP_SMEM (49152 + 1024)
__global__ __launch_bounds__(256, 2)
void prep_kernel(const float* __restrict__ q,
                 const float* __restrict__ k,
                 const float* __restrict__ W,
                 const float* __restrict__ Wd)
{
    const int t = threadIdx.x;

    if (blockIdx.y >= BH) {
        const int pb = (blockIdx.y - BH) * gridDim.x + blockIdx.x;   // 0..127
        const size_t base = (size_t)pb * 8192;
        __half2* ph = reinterpret_cast<__half2*>(g_khi);
        #pragma unroll
        for (int it = 0; it < 32; it++) {
            const size_t i = base + (size_t)it * 256 + t;
            float4 v = reinterpret_cast<const float4*>(k)[i];
            ph[2 * i]     = __floats2half2_rn(v.x, v.y);
            ph[2 * i + 1] = __floats2half2_rn(v.z, v.w);
        }
        return;
    }

    extern __shared__ char smem_raw[];
    const uint32_t smem_base = smem_u32(smem_raw);
    const uint32_t base_al   = (smem_base + 1023u) & ~1023u;
    char* tilec = smem_raw + (base_al - smem_base);
    const uint32_t Ah = base_al;
    const uint32_t Al = base_al + 16384;
    const uint32_t Mh = base_al + 32768;
    const uint32_t Ml = base_al + 40960;

    const int bh = blockIdx.y;
    const int h  = bh % HN;
    const int i0 = blockIdx.x * 128;

    const float* qb = q + (size_t)bh * SV * DV + (size_t)i0 * DV;
    const float* Wh = W + (size_t)h * DV * DV;
    const float  wd = Wd[h];

    #pragma unroll
    for (int it = 0; it < 16; it++) {
        const int idx = t + it * 256;
        const int d = idx >> 6, e = idx & 63;
        float val = wd * Wh[idx] + (d == e ? 32.0f : 0.0f);
        __half hi = __float2half(val);
        __half lo = __float2half(val - __half2float(hi));
        const uint32_t off = sw128((uint32_t)(e * 128 + d * 2));
        *reinterpret_cast<__half*>(tilec + (Mh - base_al) + off) = hi;
        *reinterpret_cast<__half*>(tilec + (Ml - base_al) + off) = lo;
    }

    #pragma unroll
    for (int it = 0; it < 4; it++) {
        const int idx = t + it * 256;
        const int row = idx >> 3;
        const int c8  = idx & 7;
        const float4 v0 = reinterpret_cast<const float4*>(qb + (size_t)row * DV)[c8 * 2];
        const float4 v1 = reinterpret_cast<const float4*>(qb + (size_t)row * DV)[c8 * 2 + 1];
        __half h0 = __float2half(v0.x), h1 = __float2half(v0.y);
        __half h2 = __float2half(v0.z), h3 = __float2half(v0.w);
        __half h4 = __float2half(v1.x), h5 = __float2half(v1.y);
        __half h6 = __float2half(v1.z), h7 = __float2half(v1.w);
        __half2 hv[4] = { __half2(h0,h1), __half2(h2,h3), __half2(h4,h5), __half2(h6,h7) };
        __half2 lv[4] = {
            __floats2half2_rn(v0.x - __half2float(h0), v0.y - __half2float(h1)),
            __floats2half2_rn(v0.z - __half2float(h2), v0.w - __half2float(h3)),
            __floats2half2_rn(v1.x - __half2float(h4), v1.y - __half2float(h5)),
            __floats2half2_rn(v1.z - __half2float(h6), v1.w - __half2float(h7)) };
        const uint32_t off = sw128((uint32_t)(row * 128 + c8 * 16));
        *reinterpret_cast<uint4*>(tilec + off)         = *reinterpret_cast<uint4*>(hv);
        *reinterpret_cast<uint4*>(tilec + 16384 + off) = *reinterpret_cast<uint4*>(lv);
    }
    __syncthreads();

    const int wid  = t >> 5;
    const int lane = t & 31;
    const int m0w  = (wid & 3) * 32;
    const int n0w  = (wid >> 2) * 32;

    float acc[2][4][4];
    #pragma unroll
    for (int m = 0; m < 2; m++)
        #pragma unroll
        for (int n = 0; n < 4; n++)
            #pragma unroll
            for (int r = 0; r < 4; r++) acc[m][n][r] = 0.0f;

    const uint32_t a_row = lane & 15;
    const uint32_t a_ch  = (lane >> 4) << 4;
    const uint32_t b_row = (lane & 7) | ((lane >> 4) << 3);
    const uint32_t b_ch  = ((lane >> 3) & 1) << 4;

    #pragma unroll
    for (int kk = 0; kk < 4; kk++) {
        const uint32_t kb = (uint32_t)kk * 32;
        uint32_t ah[2][4], al[2][4];
        #pragma unroll
        for (int m = 0; m < 2; m++) {
            const uint32_t ro = sw128((uint32_t)(m0w + m * 16 + a_row) * 128 + kb + a_ch);
            ldsm_x4(Ah + ro, ah[m][0], ah[m][1], ah[m][2], ah[m][3]);
            ldsm_x4(Al + ro, al[m][0], al[m][1], al[m][2], al[m][3]);
        }
        uint32_t bh_f[4][2], bl_f[4][2];
        #pragma unroll
        for (int tn = 0; tn < 2; tn++) {
            const uint32_t ro = sw128((uint32_t)(n0w + tn * 16 + b_row) * 128 + kb + b_ch);
            ldsm_x4(Mh + ro, bh_f[2*tn][0], bh_f[2*tn][1], bh_f[2*tn+1][0], bh_f[2*tn+1][1]);
            ldsm_x4(Ml + ro, bl_f[2*tn][0], bl_f[2*tn][1], bl_f[2*tn+1][0], bl_f[2*tn+1][1]);
        }
        #pragma unroll
        for (int m = 0; m < 2; m++)
            #pragma unroll
            for (int n = 0; n < 4; n++) {
                mma_f16(acc[m][n], ah[m], bh_f[n][0], bh_f[n][1]);
                mma_f16(acc[m][n], ah[m], bl_f[n][0], bl_f[n][1]);
                mma_f16(acc[m][n], al[m], bh_f[n][0], bh_f[n][1]);
            }
    }

    __half* oh = g_qhi + (size_t)bh * SV * DV;
    #pragma unroll
    for (int m = 0; m < 2; m++) {
        #pragma unroll
        for (int half = 0; half < 2; half++) {
            const int row = i0 + m0w + m * 16 + half * 8 + (lane >> 2);
            #pragma unroll
            for (int n = 0; n < 4; n++) {
                const int col = n0w + n * 8 + (lane & 3) * 2;
                __half2 v = __floats2half2_rn(acc[m][n][half * 2], acc[m][n][half * 2 + 1]);
                *reinterpret_cast<__half2*>(oh + (size_t)row * DV + col) = v;
            }
        }
    }
}

// ---------------------------------------------------------------------------
// Kernel 2: persistent row-strip GEMM, cp.async double-buffered B.
//   out[bh][i][j] = q''_i · k_j + Wd[h]*b[h]
// grid (1, 8, 64) = 512 CTAs; each CTA: one A tile (128xK), loop 8 j-tiles.
// 256 threads, warp tile 32x64, direct-store epilogue.
// SMEM: A 16K | B0 16K | B1 16K  (+1K align)
// ---------------------------------------------------------------------------
#define TILE_B 16384
#define SC_SMEM (3 * TILE_B + 1024)

__global__ __launch_bounds__(256, 2)
void score_mma_kernel(const float* __restrict__ b,
                      const float* __restrict__ Wd,
                      float* __restrict__ out)
{
    extern __shared__ char smem_raw[];
    const uint32_t smem_base = smem_u32(smem_raw);
    const uint32_t base_al   = (smem_base + 1023u) & ~1023u;
    const uint32_t Ab = base_al;
    const uint32_t Bb0 = base_al + TILE_B;

    const int t    = threadIdx.x;
    const int wid  = t >> 5;
    const int lane = t & 31;
    const int bh   = blockIdx.z;
    const int h    = bh % HN;
    const int i0   = blockIdx.y * 128;

    const size_t boff = (size_t)bh * SV * DV;
    const __half* qh = g_qhi + boff + (size_t)i0 * DV;
    const __half* kh = g_khi + boff;

    // per-thread load slots: 4 chunks of 16B each, idx = t + it*256
    // row = idx>>3, c16 = idx&7
    uint32_t ld_off[4];
    const __half* ld_srcA[4];
    int ld_row[4], ld_c16[4];
    #pragma unroll
    for (int it = 0; it < 4; it++) {
        const int idx = t + it * 256;
        ld_row[it] = idx >> 3;
        ld_c16[it] = idx & 7;
        ld_off[it] = sw128((uint32_t)(ld_row[it] * 128 + ld_c16[it] * 16));
        ld_srcA[it] = qh + (size_t)ld_row[it] * DV + ld_c16[it] * 8;
    }

    // ---- Prologue: cp.async A tile + B tile 0 ----
    #pragma unroll
    for (int it = 0; it < 4; it++)
        cp_async16(Ab + ld_off[it], ld_srcA[it]);
    #pragma unroll
    for (int it = 0; it < 4; it++)
        cp_async16(Bb0 + ld_off[it], kh + (size_t)ld_row[it] * DV + ld_c16[it] * 8);
    CP_COMMIT();
    CP_WAIT0();
    __syncthreads();

    const int m0w = (wid & 3) * 32;
    const int n0w = (wid >> 2) * 64;

    const uint32_t a_row = lane & 15;
    const uint32_t a_ch  = (lane >> 4) << 4;
    const uint32_t b_row = (lane & 7) | ((lane >> 4) << 3);
    const uint32_t b_ch  = ((lane >> 3) & 1) << 4;

    const float cbias = Wd[h] * b[h];
    float* obase = out + (size_t)bh * SV * SV;

    for (int jt = 0; jt < 8; jt++) {
        const int p = jt & 1;
        const uint32_t Bb = Bb0 + (uint32_t)p * TILE_B;

        // prefetch next B tile into the other buffer
        if (jt < 7) {
            const __half* kn = kh + (size_t)(jt + 1) * 128 * DV;
            const uint32_t Bn = Bb0 + (uint32_t)(1 - p) * TILE_B;
            #pragma unroll
            for (int it = 0; it < 4; it++)
                cp_async16(Bn + ld_off[it], kn + (size_t)ld_row[it] * DV + ld_c16[it] * 8);
            CP_COMMIT();
        }

        // ---- compute 128x128 tile ----
        float acc[2][8][4];
        #pragma unroll
        for (int m = 0; m < 2; m++)
            #pragma unroll
            for (int n = 0; n < 8; n++)
                #pragma unroll
                for (int r = 0; r < 4; r++) acc[m][n][r] = 0.0f;

        #pragma unroll
        for (int kk = 0; kk < 4; kk++) {
            const uint32_t kb = (uint32_t)kk * 32;
            uint32_t a[2][4];
            #pragma unroll
            for (int m = 0; m < 2; m++) {
                const uint32_t ro = sw128((uint32_t)(m0w + m * 16 + a_row) * 128 + kb + a_ch);
                ldsm_x4(Ab + ro, a[m][0], a[m][1], a[m][2], a[m][3]);
            }
            uint32_t bf[8][2];
            #pragma unroll
            for (int tn = 0; tn < 4; tn++) {
                const uint32_t ro = sw128((uint32_t)(n0w + tn * 16 + b_row) * 128 + kb + b_ch);
                ldsm_x4(Bb + ro, bf[2*tn][0], bf[2*tn][1], bf[2*tn+1][0], bf[2*tn+1][1]);
            }
            #pragma unroll
            for (int m = 0; m < 2; m++)
                #pragma unroll
                for (int n = 0; n < 8; n++)
                    mma_f16(acc[m][n], a[m], bf[n][0], bf[n][1]);
        }

        // ---- direct-store epilogue ----
        const int row_base = i0 + m0w + (lane >> 2);
        const int col_base = jt * 128 + n0w + (lane & 3) * 2;
        #pragma unroll
        for (int m = 0; m < 2; m++) {
            #pragma unroll
            for (int half = 0; half < 2; half++) {
                const int r = row_base + m * 16 + half * 8;
                float* prow = obase + (size_t)r * SV + col_base;
                #pragma unroll
                for (int n = 0; n < 8; n++) {
                    float2 v;
                    v.x = acc[m][n][half * 2 + 0] + cbias;
                    v.y = acc[m][n][half * 2 + 1] + cbias;
                    *reinterpret_cast<float2*>(prow + n * 8) = v;
                }
            }
        }

        if (jt < 7) {
            CP_WAIT0();
            __syncthreads();
        }
    }
}

// ---------------------------------------------------------------------------
extern "C" void kernel_launch(void* const* d_in, const int* in_sizes, int n_in,
                              void* d_out, int out_size)
{
    const float* q  = (const float*)d_in[0];
    const float* k  = (const float*)d_in[1];
    const float* W  = (const float*)d_in[2];
    const float* b  = (const float*)d_in[3];
    const float* Wd = (const float*)d_in[4];
    float* out = (float*)d_out;

    cudaFuncSetAttribute(prep_kernel,
                         cudaFuncAttributeMaxDynamicSharedMemorySize, PREP_SMEM);
    cudaFuncSetAttribute(score_mma_kernel,
                         cudaFuncAttributeMaxDynamicSharedMemorySize, SC_SMEM);

    dim3 g1(8, BH + 16);
    prep_kernel<<<g1, 256, PREP_SMEM>>>(q, k, W, Wd);

    dim3 g3(1, SV / 128, BH);
    score_mma_kernel<<<g3, 256, SC_SMEM>>>(b, Wd, out);
}

// round 9
// speedup vs baseline: 1.2760x; 1.0004x over previous
#include <cuda_runtime.h>
#include <cuda_fp16.h>
#include <cstdint>
#include <cstddef>

// Problem constants
#define BV 4
#define HN 16
#define SV 1024
#define DV 64
#define BH (BV*HN)

// fp16 k operand (device scratch; no allocation)
__device__ __half g_khi[(size_t)BH * SV * DV];

__device__ __forceinline__ uint32_t smem_u32(const void* p) {
    uint32_t a;
    asm("{ .reg .u64 t; cvta.to.shared.u64 t, %1; cvt.u32.u64 %0, t; }" : "=r"(a) : "l"(p));
    return a;
}
__device__ __forceinline__ uint32_t sw128(uint32_t off) {
    return off ^ ((off >> 3) & 0x70);
}
__device__ __forceinline__ void ldsm_x4(uint32_t addr, uint32_t& r0, uint32_t& r1,
                                        uint32_t& r2, uint32_t& r3) {
    asm volatile("ldmatrix.sync.aligned.m8n8.x4.shared.b16 {%0,%1,%2,%3}, [%4];"
                 : "=r"(r0), "=r"(r1), "=r"(r2), "=r"(r3) : "r"(addr));
}
__device__ __forceinline__ void mma_f16(float* c, const uint32_t* a,
                                        uint32_t b0, uint32_t b1) {
    asm volatile(
        "mma.sync.aligned.m16n8k16.row.col.f32.f16.f16.f32 "
        "{%0,%1,%2,%3}, {%4,%5,%6,%7}, {%8,%9}, {%0,%1,%2,%3};"
        : "+f"(c[0]), "+f"(c[1]), "+f"(c[2]), "+f"(c[3])
        : "r"(a[0]), "r"(a[1]), "r"(a[2]), "r"(a[3]), "r"(b0), "r"(b1));
}
__device__ __forceinline__ void cp_async16(uint32_t smem_dst, const void* gsrc) {
    asm volatile("cp.async.cg.shared.global [%0], [%1], 16;"
                 :: "r"(smem_dst), "l"(gsrc));
}
#define CP_COMMIT() asm volatile("cp.async.commit_group;" ::: "memory")
#define CP_WAIT0()  asm volatile("cp.async.wait_group 0;"  ::: "memory")
__device__ __forceinline__ void stg_cs_v2(float* p, float x, float y) {
    asm volatile("st.global.cs.v2.f32 [%0], {%1, %2};"
                 :: "l"(p), "f"(x), "f"(y) : "memory");
}

// ---------------------------------------------------------------------------
// Kernel 1: k -> fp16 convert. grid 128, 256 threads.
// ---------------------------------------------------------------------------
__global__ __launch_bounds__(256)
void kconv_kernel(const float* __restrict__ k)
{
    const int t = threadIdx.x;
    const size_t base = (size_t)blockIdx.x * 8192;
    __half2* ph = reinterpret_cast<__half2*>(g_khi);
    #pragma unroll
    for (int it = 0; it < 32; it++) {
        const size_t i = base + (size_t)it * 256 + t;
        float4 v = reinterpret_cast<const float4*>(k)[i];
        ph[2 * i]     = __floats2half2_rn(v.x, v.y);
        ph[2 * i + 1] = __floats2half2_rn(v.z, v.w);
    }
}

// ---------------------------------------------------------------------------
// Kernel 2: persistent row-strip GEMM with fused fold prologue.
//   Prologue: q''(strip) = q @ (32*I + Wd[h]*W[h])  via 3-pass fp16-split MMA,
//             result -> smem A tile (fp16, SW128).
//   Main: 8 j-tiles, cp.async double-buffered B, warp tile 32x64,
//         .cs streaming stores.
// grid (1, 8, 64) = 512 CTAs, 256 threads.
// SMEM: Qh 16K | Ql 16K | Mh 8K | Ml 8K | A 16K | B0 16K | B1 16K = 96K
// ---------------------------------------------------------------------------
#define TILE_B 16384
#define SC_SMEM (98304 + 1024)

__global__ __launch_bounds__(256, 2)
void score_mma_kernel(const float* __restrict__ q,
                      const float* __restrict__ W,
                      const float* __restrict__ b,
                      const float* __restrict__ Wd,
                      float* __restrict__ out)
{
    extern __shared__ char smem_raw[];
    const uint32_t smem_base = smem_u32(smem_raw);
    const uint32_t base_al   = (smem_base + 1023u) & ~1023u;
    char* tilec = smem_raw + (base_al - smem_base);
    const uint32_t Qh  = base_al;
    const uint32_t Ql  = base_al + 16384;
    const uint32_t Mh  = base_al + 32768;
    const uint32_t Ml  = base_al + 40960;
    const uint32_t Ab  = base_al + 49152;
    const uint32_t Bb0 = base_al + 65536;

    const int t    = threadIdx.x;
    const int wid  = t >> 5;
    const int lane = t & 31;
    const int bh   = blockIdx.z;
    const int h    = bh % HN;
    const int i0   = blockIdx.y * 128;

    const size_t boff = (size_t)bh * SV * DV;
    const __half* kh = g_khi + boff;

    // per-thread 16B load slots (idx = t + it*256; row = idx>>3, c16 = idx&7)
    uint32_t ld_off[4];
    int ld_row[4], ld_c16[4];
    #pragma unroll
    for (int it = 0; it < 4; it++) {
        const int idx = t + it * 256;
        ld_row[it] = idx >> 3;
        ld_c16[it] = idx & 7;
        ld_off[it] = sw128((uint32_t)(ld_row[it] * 128 + ld_c16[it] * 16));
    }

    // ---- Prefetch B tile 0 immediately (overlaps the whole fold) ----
    #pragma unroll
    for (int it = 0; it < 4; it++)
        cp_async16(Bb0 + ld_off[it], kh + (size_t)ld_row[it] * DV + ld_c16[it] * 8);
    CP_COMMIT();

    // =========================== FOLD PROLOGUE ===========================
    {
        const float* qb = q + boff + (size_t)i0 * DV;
        const float* Wh = W + (size_t)h * DV * DV;
        const float  wd = Wd[h];

        // Build M = 32*I + wd*W, transposed [e][d], fp16 hi/lo, swizzled
        #pragma unroll
        for (int it = 0; it < 16; it++) {
            const int idx = t + it * 256;          // d*64+e
            const int d = idx >> 6, e = idx & 63;
            float val = wd * Wh[idx] + (d == e ? 32.0f : 0.0f);
            __half hi = __float2half(val);
            __half lo = __float2half(val - __half2float(hi));
            const uint32_t off = sw128((uint32_t)(e * 128 + d * 2));
            *reinterpret_cast<__half*>(tilec + (Mh - base_al) + off) = hi;
            *reinterpret_cast<__half*>(tilec + (Ml - base_al) + off) = lo;
        }

        // Load q strip (128x64 f32), split hi/lo into swizzled fp16 tiles
        #pragma unroll
        for (int it = 0; it < 4; it++) {
            const float4 v0 = reinterpret_cast<const float4*>(qb + (size_t)ld_row[it] * DV)[ld_c16[it] * 2];
            const float4 v1 = reinterpret_cast<const float4*>(qb + (size_t)ld_row[it] * DV)[ld_c16[it] * 2 + 1];
            __half h0 = __float2half(v0.x), h1 = __float2half(v0.y);
            __half h2 = __float2half(v0.z), h3 = __float2half(v0.w);
            __half h4 = __float2half(v1.x), h5 = __float2half(v1.y);
            __half h6 = __float2half(v1.z), h7 = __float2half(v1.w);
            __half2 hv[4] = { __half2(h0,h1), __half2(h2,h3), __half2(h4,h5), __half2(h6,h7) };
            __half2 lv[4] = {
                __floats2half2_rn(v0.x - __half2float(h0), v0.y - __half2float(h1)),
                __floats2half2_rn(v0.z - __half2float(h2), v0.w - __half2float(h3)),
                __floats2half2_rn(v1.x - __half2float(h4), v1.y - __half2float(h5)),
                __floats2half2_rn(v1.z - __half2float(h6), v1.w - __half2float(h7)) };
            *reinterpret_cast<uint4*>(tilec + (Qh - base_al) + ld_off[it]) = *reinterpret_cast<uint4*>(hv);
            *reinterpret_cast<uint4*>(tilec + (Ql - base_al) + ld_off[it]) = *reinterpret_cast<uint4*>(lv);
        }
        __syncthreads();

        // fold MMA: warp tile 32x32, warp grid 4(M) x 2(N)
        const int m0w = (wid & 3) * 32;
        const int n0w = (wid >> 2) * 32;

        float acc[2][4][4];
        #pragma unroll
        for (int m = 0; m < 2; m++)
            #pragma unroll
            for (int n = 0; n < 4; n++)
                #pragma unroll
                for (int r = 0; r < 4; r++) acc[m][n][r] = 0.0f;

        const uint32_t a_row = lane & 15;
        const uint32_t a_ch  = (lane >> 4) << 4;
        const uint32_t b_row = (lane & 7) | ((lane >> 4) << 3);
        const uint32_t b_ch  = ((lane >> 3) & 1) << 4;

        #pragma unroll
        for (int kk = 0; kk < 4; kk++) {
            const uint32_t kb = (uint32_t)kk * 32;
            uint32_t ah[2][4], al[2][4];
            #pragma unroll
            for (int m = 0; m < 2; m++) {
                const uint32_t ro = sw128((uint32_t)(m0w + m * 16 + a_row) * 128 + kb + a_ch);
                ldsm_x4(Qh + ro, ah[m][0], ah[m][1], ah[m][2], ah[m][3]);
                ldsm_x4(Ql + ro, al[m][0], al[m][1], al[m][2], al[m][3]);
            }
            uint32_t bh_f[4][2], bl_f[4][2];
            #pragma unroll
            for (int tn = 0; tn < 2; tn++) {
                const uint32_t ro = sw128((uint32_t)(n0w + tn * 16 + b_row) * 128 + kb + b_ch);
                ldsm_x4(Mh + ro, bh_f[2*tn][0], bh_f[2*tn][1], bh_f[2*tn+1][0], bh_f[2*tn+1][1]);
                ldsm_x4(Ml + ro, bl_f[2*tn][0], bl_f[2*tn][1], bl_f[2*tn+1][0], bl_f[2*tn+1][1]);
            }
            #pragma unroll
            for (int m = 0; m < 2; m++)
                #pragma unroll
                for (int n = 0; n < 4; n++) {
                    mma_f16(acc[m][n], ah[m], bh_f[n][0], bh_f[n][1]);
                    mma_f16(acc[m][n], ah[m], bl_f[n][0], bl_f[n][1]);
                    mma_f16(acc[m][n], al[m], bh_f[n][0], bh_f[n][1]);
                }
        }
        __syncthreads();   // everyone done reading Qh/Ql/M before A overwr... (A is separate; sync orders STS below vs ldsm above across warps)

        // Write q'' tile to smem A (fp16, SW128)
        #pragma unroll
        for (int m = 0; m < 2; m++) {
            #pragma unroll
            for (int half = 0; half < 2; half++) {
                const int row = m0w + m * 16 + half * 8 + (lane >> 2);
                #pragma unroll
                for (int n = 0; n < 4; n++) {
                    const int col = n0w + n * 8 + (lane & 3) * 2;
                    __half2 v = __floats2half2_rn(acc[m][n][half * 2], acc[m][n][half * 2 + 1]);
                    const uint32_t off = sw128((uint32_t)(row * 128 + col * 2));
                    *reinterpret_cast<__half2*>(tilec + (Ab - base_al) + off) = v;
                }
            }
        }
    }

    CP_WAIT0();          // B tile 0 resident
    __syncthreads();     // A tile + B0 visible to all warps

    // ============================ J-LOOP ============================
    const int m0w = (wid & 3) * 32;
    const int n0w = (wid >> 2) * 64;

    const uint32_t a_row = lane & 15;
    const uint32_t a_ch  = (lane >> 4) << 4;
    const uint32_t b_row = (lane & 7) | ((lane >> 4) << 3);
    const uint32_t b_ch  = ((lane >> 3) & 1) << 4;

    const float cbias = Wd[h] * b[h];
    float* obase = out + (size_t)bh * SV * SV;

    for (int jt = 0; jt < 8; jt++) {
        const int p = jt & 1;
        const uint32_t Bb = Bb0 + (uint32_t)p * TILE_B;

        // prefetch next B tile into the other buffer
        if (jt < 7) {
            const __half* kn = kh + (size_t)(jt + 1) * 128 * DV;
            const uint32_t Bn = Bb0 + (uint32_t)(1 - p) * TILE_B;
            #pragma unroll
            for (int it = 0; it < 4; it++)
                cp_async16(Bn + ld_off[it], kn + (size_t)ld_row[it] * DV + ld_c16[it] * 8);
            CP_COMMIT();
        }

        // ---- compute 128x128 tile ----
        float acc[2][8][4];
        #pragma unroll
        for (int m = 0; m < 2; m++)
            #pragma unroll
            for (int n = 0; n < 8; n++)
                #pragma unroll
                for (int r = 0; r < 4; r++) acc[m][n][r] = 0.0f;

        #pragma unroll
        for (int kk = 0; kk < 4; kk++) {
            const uint32_t kb = (uint32_t)kk * 32;
            uint32_t a[2][4];
            #pragma unroll
            for (int m = 0; m < 2; m++) {
                const uint32_t ro = sw128((uint32_t)(m0w + m * 16 + a_row) * 128 + kb + a_ch);
                ldsm_x4(Ab + ro, a[m][0], a[m][1], a[m][2], a[m][3]);
            }
            uint32_t bf[8][2];
            #pragma unroll
            for (int tn = 0; tn < 4; tn++) {
                const uint32_t ro = sw128((uint32_t)(n0w + tn * 16 + b_row) * 128 + kb + b_ch);
                ldsm_x4(Bb + ro, bf[2*tn][0], bf[2*tn][1], bf[2*tn+1][0], bf[2*tn+1][1]);
            }
            #pragma unroll
            for (int m = 0; m < 2; m++)
                #pragma unroll
                for (int n = 0; n < 8; n++)
                    mma_f16(acc[m][n], a[m], bf[n][0], bf[n][1]);
        }

        // ---- streaming-store epilogue ----
        const int row_base = i0 + m0w + (lane >> 2);
        const int col_base = jt * 128 + n0w + (lane & 3) * 2;
        #pragma unroll
        for (int m = 0; m < 2; m++) {
            #pragma unroll
            for (int half = 0; half < 2; half++) {
                const int r = row_base + m * 16 + half * 8;
                float* prow = obase + (size_t)r * SV + col_base;
                #pragma unroll
                for (int n = 0; n < 8; n++)
                    stg_cs_v2(prow + n * 8,
                              acc[m][n][half * 2 + 0] + cbias,
                              acc[m][n][half * 2 + 1] + cbias);
            }
        }

        if (jt < 7) {
            CP_WAIT0();
            __syncthreads();
        }
    }
}

// ---------------------------------------------------------------------------
extern "C" void kernel_launch(void* const* d_in, const int* in_sizes, int n_in,
                              void* d_out, int out_size)
{
    const float* q  = (const float*)d_in[0];
    const float* k  = (const float*)d_in[1];
    const float* W  = (const float*)d_in[2];
    const float* b  = (const float*)d_in[3];
    const float* Wd = (const float*)d_in[4];
    float* out = (float*)d_out;

    cudaFuncSetAttribute(score_mma_kernel,
                         cudaFuncAttributeMaxDynamicSharedMemorySize, SC_SMEM);

    kconv_kernel<<<128, 256>>>(k);

    dim3 g3(1, SV / 128, BH);
    score_mma_kernel<<<g3, 256, SC_SMEM>>>(q, W, b, Wd, out);
}

// round 10
// speedup vs baseline: 1.3070x; 1.0243x over previous
#include <cuda_runtime.h>
#include <cuda_fp16.h>
#include <cstdint>
#include <cstddef>

// Problem constants
#define BV 4
#define HN 16
#define SV 1024
#define DV 64
#define BH (BV*HN)

// fp16 k operand (device scratch; no allocation)
__device__ __half g_khi[(size_t)BH * SV * DV];

__device__ __forceinline__ uint32_t smem_u32(const void* p) {
    uint32_t a;
    asm("{ .reg .u64 t; cvta.to.shared.u64 t, %1; cvt.u32.u64 %0, t; }" : "=r"(a) : "l"(p));
    return a;
}
__device__ __forceinline__ uint32_t sw128(uint32_t off) {
    return off ^ ((off >> 3) & 0x70);
}
__device__ __forceinline__ void ldsm_x4(uint32_t addr, uint32_t& r0, uint32_t& r1,
                                        uint32_t& r2, uint32_t& r3) {
    asm volatile("ldmatrix.sync.aligned.m8n8.x4.shared.b16 {%0,%1,%2,%3}, [%4];"
                 : "=r"(r0), "=r"(r1), "=r"(r2), "=r"(r3) : "r"(addr));
}
__device__ __forceinline__ void mma_f16(float* c, const uint32_t* a,
                                        uint32_t b0, uint32_t b1) {
    asm volatile(
        "mma.sync.aligned.m16n8k16.row.col.f32.f16.f16.f32 "
        "{%0,%1,%2,%3}, {%4,%5,%6,%7}, {%8,%9}, {%0,%1,%2,%3};"
        : "+f"(c[0]), "+f"(c[1]), "+f"(c[2]), "+f"(c[3])
        : "r"(a[0]), "r"(a[1]), "r"(a[2]), "r"(a[3]), "r"(b0), "r"(b1));
}
__device__ __forceinline__ void cp_async16(uint32_t smem_dst, const void* gsrc) {
    asm volatile("cp.async.cg.shared.global [%0], [%1], 16;"
                 :: "r"(smem_dst), "l"(gsrc));
}
#define CP_COMMIT() asm volatile("cp.async.commit_group;" ::: "memory")
#define CP_WAIT0()  asm volatile("cp.async.wait_group 0;"  ::: "memory")
#define BAR_GRP(id) asm volatile("bar.sync %0, 128;" :: "r"(id) : "memory")

// ---------------------------------------------------------------------------
// Kernel 1: k -> fp16 convert. grid 128, 256 threads.
// ---------------------------------------------------------------------------
__global__ __launch_bounds__(256)
void kconv_kernel(const float* __restrict__ k)
{
    const int t = threadIdx.x;
    const size_t base = (size_t)blockIdx.x * 8192;
    __half2* ph = reinterpret_cast<__half2*>(g_khi);
    #pragma unroll
    for (int it = 0; it < 32; it++) {
        const size_t i = base + (size_t)it * 256 + t;
        float4 v = reinterpret_cast<const float4*>(k)[i];
        ph[2 * i]     = __floats2half2_rn(v.x, v.y);
        ph[2 * i + 1] = __floats2half2_rn(v.z, v.w);
    }
}

// ---------------------------------------------------------------------------
// Kernel 2: persistent row-strip GEMM, fused fold prologue, group-decoupled
// j-loop, per-warp staged coalesced stores.
// grid (1, 8, 64) = 512 CTAs, 256 threads.
// SMEM layout (from 1K-aligned base):
//   Qh 16K | Ql 16K | M(hi 8K, lo 8K) -> overlaid by STAGE 16K in j-loop |
//   A 16K | B: grp0{p0,p1} grp1{p0,p1} 4x8K = 32K          total 96K
// ---------------------------------------------------------------------------
#define OFF_QH 0
#define OFF_QL 16384
#define OFF_MH 32768
#define OFF_ML 40960
#define OFF_ST 32768
#define OFF_A  49152
#define OFF_B  65536
#define SC_SMEM (98304 + 1024)

__global__ __launch_bounds__(256, 2)
void score_mma_kernel(const float* __restrict__ q,
                      const float* __restrict__ W,
                      const float* __restrict__ b,
                      const float* __restrict__ Wd,
                      float* __restrict__ out)
{
    extern __shared__ char smem_raw[];
    const uint32_t smem_base = smem_u32(smem_raw);
    const uint32_t base_al   = (smem_base + 1023u) & ~1023u;
    char* tilec = smem_raw + (base_al - smem_base);

    const int t    = threadIdx.x;
    const int wid  = t >> 5;
    const int lane = t & 31;
    const int grp  = t >> 7;          // 0: warps 0-3, 1: warps 4-7
    const int tg   = t & 127;
    const int bh   = blockIdx.z;
    const int h    = bh % HN;
    const int i0   = blockIdx.y * 128;

    const size_t boff = (size_t)bh * SV * DV;
    const __half* kh = g_khi + boff;

    // B half-tile load slots (64 rows x 128B per group; 4 x 16B per thread)
    uint32_t bld_off[4];
    int bld_row[4], bld_c16[4];
    #pragma unroll
    for (int it = 0; it < 4; it++) {
        const int idx = tg + it * 128;          // 0..511
        bld_row[it] = idx >> 3;                 // 0..63
        bld_c16[it] = idx & 7;
        bld_off[it] = sw128((uint32_t)(bld_row[it] * 128 + bld_c16[it] * 16));
    }
    const uint32_t Bg = base_al + OFF_B + (uint32_t)grp * 16384;

    // ---- Prefetch B tile 0 (own group half) immediately; overlaps fold ----
    {
        const __half* src = kh + (size_t)grp * 64 * DV;
        #pragma unroll
        for (int it = 0; it < 4; it++)
            cp_async16(Bg + bld_off[it], src + (size_t)bld_row[it] * DV + bld_c16[it] * 8);
        CP_COMMIT();
    }

    // =========================== FOLD PROLOGUE ===========================
    {
        const float* qb = q + boff + (size_t)i0 * DV;
        const float* Wh = W + (size_t)h * DV * DV;
        const float  wd = Wd[h];

        // Build M = 32*I + wd*W, transposed [e][d], fp16 hi/lo, swizzled
        #pragma unroll
        for (int it = 0; it < 16; it++) {
            const int idx = t + it * 256;          // d*64+e
            const int d = idx >> 6, e = idx & 63;
            float val = wd * Wh[idx] + (d == e ? 32.0f : 0.0f);
            __half hi = __float2half(val);
            __half lo = __float2half(val - __half2float(hi));
            const uint32_t off = sw128((uint32_t)(e * 128 + d * 2));
            *reinterpret_cast<__half*>(tilec + OFF_MH + off) = hi;
            *reinterpret_cast<__half*>(tilec + OFF_ML + off) = lo;
        }

        // Load q strip (128x64 f32), split hi/lo into swizzled fp16 tiles
        #pragma unroll
        for (int it = 0; it < 4; it++) {
            const int idx = t + it * 256;          // 0..1023
            const int row = idx >> 3;
            const int c16 = idx & 7;
            const uint32_t off = sw128((uint32_t)(row * 128 + c16 * 16));
            const float4 v0 = reinterpret_cast<const float4*>(qb + (size_t)row * DV)[c16 * 2];
            const float4 v1 = reinterpret_cast<const float4*>(qb + (size_t)row * DV)[c16 * 2 + 1];
            __half h0 = __float2half(v0.x), h1 = __float2half(v0.y);
            __half h2 = __float2half(v0.z), h3 = __float2half(v0.w);
            __half h4 = __float2half(v1.x), h5 = __float2half(v1.y);
            __half h6 = __float2half(v1.z), h7 = __float2half(v1.w);
            __half2 hv[4] = { __half2(h0,h1), __half2(h2,h3), __half2(h4,h5), __half2(h6,h7) };
            __half2 lv[4] = {
                __floats2half2_rn(v0.x - __half2float(h0), v0.y - __half2float(h1)),
                __floats2half2_rn(v0.z - __half2float(h2), v0.w - __half2float(h3)),
                __floats2half2_rn(v1.x - __half2float(h4), v1.y - __half2float(h5)),
                __floats2half2_rn(v1.z - __half2float(h6), v1.w - __half2float(h7)) };
            *reinterpret_cast<uint4*>(tilec + OFF_QH + off) = *reinterpret_cast<uint4*>(hv);
            *reinterpret_cast<uint4*>(tilec + OFF_QL + off) = *reinterpret_cast<uint4*>(lv);
        }
        __syncthreads();

        // fold MMA: warp tile 32x32, warp grid 4(M) x 2(N)
        const int m0w = (wid & 3) * 32;
        const int n0w = (wid >> 2) * 32;

        float acc[2][4][4];
        #pragma unroll
        for (int m = 0; m < 2; m++)
            #pragma unroll
            for (int n = 0; n < 4; n++)
                #pragma unroll
                for (int r = 0; r < 4; r++) acc[m][n][r] = 0.0f;

        const uint32_t a_row = lane & 15;
        const uint32_t a_ch  = (lane >> 4) << 4;
        const uint32_t b_row = (lane & 7) | ((lane >> 4) << 3);
        const uint32_t b_ch  = ((lane >> 3) & 1) << 4;

        #pragma unroll
        for (int kk = 0; kk < 4; kk++) {
            const uint32_t kb = (uint32_t)kk * 32;
            uint32_t ah[2][4], al[2][4];
            #pragma unroll
            for (int m = 0; m < 2; m++) {
                const uint32_t ro = sw128((uint32_t)(m0w + m * 16 + a_row) * 128 + kb + a_ch);
                ldsm_x4(base_al + OFF_QH + ro, ah[m][0], ah[m][1], ah[m][2], ah[m][3]);
                ldsm_x4(base_al + OFF_QL + ro, al[m][0], al[m][1], al[m][2], al[m][3]);
            }
            uint32_t bh_f[4][2], bl_f[4][2];
            #pragma unroll
            for (int tn = 0; tn < 2; tn++) {
                const uint32_t ro = sw128((uint32_t)(n0w + tn * 16 + b_row) * 128 + kb + b_ch);
                ldsm_x4(base_al + OFF_MH + ro, bh_f[2*tn][0], bh_f[2*tn][1], bh_f[2*tn+1][0], bh_f[2*tn+1][1]);
                ldsm_x4(base_al + OFF_ML + ro, bl_f[2*tn][0], bl_f[2*tn][1], bl_f[2*tn+1][0], bl_f[2*tn+1][1]);
            }
            #pragma unroll
            for (int m = 0; m < 2; m++)
                #pragma unroll
                for (int n = 0; n < 4; n++) {
                    mma_f16(acc[m][n], ah[m], bh_f[n][0], bh_f[n][1]);
                    mma_f16(acc[m][n], ah[m], bl_f[n][0], bl_f[n][1]);
                    mma_f16(acc[m][n], al[m], bh_f[n][0], bh_f[n][1]);
                }
        }
        __syncthreads();   // all M/Q reads done before A write (& STAGE overlay later)

        // Write q'' tile to smem A (fp16, SW128)
        #pragma unroll
        for (int m = 0; m < 2; m++) {
            #pragma unroll
            for (int half = 0; half < 2; half++) {
                const int row = m0w + m * 16 + half * 8 + (lane >> 2);
                #pragma unroll
                for (int n = 0; n < 4; n++) {
                    const int col = n0w + n * 8 + (lane & 3) * 2;
                    __half2 v = __floats2half2_rn(acc[m][n][half * 2], acc[m][n][half * 2 + 1]);
                    const uint32_t off = sw128((uint32_t)(row * 128 + col * 2));
                    *reinterpret_cast<__half2*>(tilec + OFF_A + off) = v;
                }
            }
        }
    }

    CP_WAIT0();          // own-group B0 chunks resident
    __syncthreads();     // A visible to all; groups decouple from here

    // ============================ J-LOOP ============================
    const int m0w = (wid & 3) * 32;

    const uint32_t a_row = lane & 15;
    const uint32_t a_ch  = (lane >> 4) << 4;
    const uint32_t b_row = (lane & 7) | ((lane >> 4) << 3);
    const uint32_t b_ch  = ((lane >> 3) & 1) << 4;

    const float cbias = Wd[h] * b[h];
    float* obase = out + (size_t)bh * SV * SV;
    char* stg = tilec + OFF_ST + wid * 2048;    // per-warp staging (8 rows x 256B)

    const int rsub = lane >> 2;
    const int l3   = lane & 3;

    for (int jt = 0; jt < 8; jt++) {
        const int p = jt & 1;
        const uint32_t Bb = Bg + (uint32_t)p * 8192;

        // prefetch next half-tile into the other buffer (own group)
        if (jt < 7) {
            const __half* kn = kh + (size_t)((jt + 1) * 128 + grp * 64) * DV;
            const uint32_t Bn = Bg + (uint32_t)(1 - p) * 8192;
            #pragma unroll
            for (int it = 0; it < 4; it++)
                cp_async16(Bn + bld_off[it], kn + (size_t)bld_row[it] * DV + bld_c16[it] * 8);
            CP_COMMIT();
        }

        // ---- compute 128x64 warp-group slab (warp tile 32x64) ----
        float acc[2][8][4];
        #pragma unroll
        for (int m = 0; m < 2; m++)
            #pragma unroll
            for (int n = 0; n < 8; n++)
                #pragma unroll
                for (int r = 0; r < 4; r++) acc[m][n][r] = 0.0f;

        #pragma unroll
        for (int kk = 0; kk < 4; kk++) {
            const uint32_t kb = (uint32_t)kk * 32;
            uint32_t a[2][4];
            #pragma unroll
            for (int m = 0; m < 2; m++) {
                const uint32_t ro = sw128((uint32_t)(m0w + m * 16 + a_row) * 128 + kb + a_ch);
                ldsm_x4(base_al + OFF_A + ro, a[m][0], a[m][1], a[m][2], a[m][3]);
            }
            uint32_t bf[8][2];
            #pragma unroll
            for (int tn = 0; tn < 4; tn++) {
                const uint32_t ro = sw128((uint32_t)(tn * 16 + b_row) * 128 + kb + b_ch);
                ldsm_x4(Bb + ro, bf[2*tn][0], bf[2*tn][1], bf[2*tn+1][0], bf[2*tn+1][1]);
            }
            #pragma unroll
            for (int m = 0; m < 2; m++)
                #pragma unroll
                for (int n = 0; n < 8; n++)
                    mma_f16(acc[m][n], a[m], bf[n][0], bf[n][1]);
        }

        // ---- staged epilogue: per-warp swizzled STS -> coalesced STG.128 ----
        #pragma unroll
        for (int m = 0; m < 2; m++) {
            #pragma unroll
            for (int half = 0; half < 2; half++) {
                // STS: 8 rows x 64 floats, granule (8B) swizzle g' = ((n^rsub)&7)*4+l3
                #pragma unroll
                for (int n = 0; n < 8; n++) {
                    const uint32_t gp = (uint32_t)((((n ^ rsub) & 7) * 4 + l3) * 8);
                    float2 v;
                    v.x = acc[m][n][half * 2 + 0] + cbias;
                    v.y = acc[m][n][half * 2 + 1] + cbias;
                    *reinterpret_cast<float2*>(stg + rsub * 256 + gp) = v;
                }
                __syncwarp();
                // LDS.128 + coalesced STG.128: 2 rows per instr
                const int rr = (lane >> 4);         // 0/1
                const int cc = lane & 15;           // 16B chunk
                #pragma unroll
                for (int i2 = 0; i2 < 4; i2++) {
                    const int r = i2 * 2 + rr;
                    const uint32_t gp = (uint32_t)(((((cc >> 1) ^ r) & 7) * 4 + (cc & 1) * 2) * 8);
                    float4 v = *reinterpret_cast<const float4*>(stg + r * 256 + gp);
                    const int grow = i0 + m0w + m * 16 + half * 8 + r;
                    const int gcol = jt * 128 + grp * 64 + cc * 4;
                    asm volatile("st.global.cs.v4.f32 [%0], {%1,%2,%3,%4};"
                                 :: "l"(obase + (size_t)grow * SV + gcol),
                                    "f"(v.x), "f"(v.y), "f"(v.z), "f"(v.w) : "memory");
                }
                __syncwarp();
            }
        }

        if (jt < 7) {
            CP_WAIT0();
            BAR_GRP(grp + 1);     // group-scoped barrier (128 threads)
        }
    }
}

// ---------------------------------------------------------------------------
extern "C" void kernel_launch(void* const* d_in, const int* in_sizes, int n_in,
                              void* d_out, int out_size)
{
    const float* q  = (const float*)d_in[0];
    const float* k  = (const float*)d_in[1];
    const float* W  = (const float*)d_in[2];
    const float* b  = (const float*)d_in[3];
    const float* Wd = (const float*)d_in[4];
    float* out = (float*)d_out;

    cudaFuncSetAttribute(score_mma_kernel,
                         cudaFuncAttributeMaxDynamicSharedMemorySize, SC_SMEM);

    kconv_kernel<<<128, 256>>>(k);

    dim3 g3(1, SV / 128, BH);
    score_mma_kernel<<<g3, 256, SC_SMEM>>>(q, W, b, Wd, out);
}

// round 11
// speedup vs baseline: 1.3905x; 1.0639x over previous
#include <cuda_runtime.h>
#include <cuda_fp16.h>
#include <cstdint>
#include <cstddef>

// Problem constants
#define BV 4
#define HN 16
#define SV 1024
#define DV 64
#define BH (BV*HN)

// fp16 k operand (device scratch; no allocation)
__device__ __half g_khi[(size_t)BH * SV * DV];

__device__ __forceinline__ uint32_t smem_u32(const void* p) {
    uint32_t a;
    asm("{ .reg .u64 t; cvta.to.shared.u64 t, %1; cvt.u32.u64 %0, t; }" : "=r"(a) : "l"(p));
    return a;
}
__device__ __forceinline__ uint32_t sw128(uint32_t off) {
    return off ^ ((off >> 3) & 0x70);
}
__device__ __forceinline__ void ldsm_x4(uint32_t addr, uint32_t& r0, uint32_t& r1,
                                        uint32_t& r2, uint32_t& r3) {
    asm volatile("ldmatrix.sync.aligned.m8n8.x4.shared.b16 {%0,%1,%2,%3}, [%4];"
                 : "=r"(r0), "=r"(r1), "=r"(r2), "=r"(r3) : "r"(addr));
}
__device__ __forceinline__ void mma_f16(float* c, const uint32_t* a,
                                        uint32_t b0, uint32_t b1) {
    asm volatile(
        "mma.sync.aligned.m16n8k16.row.col.f32.f16.f16.f32 "
        "{%0,%1,%2,%3}, {%4,%5,%6,%7}, {%8,%9}, {%0,%1,%2,%3};"
        : "+f"(c[0]), "+f"(c[1]), "+f"(c[2]), "+f"(c[3])
        : "r"(a[0]), "r"(a[1]), "r"(a[2]), "r"(a[3]), "r"(b0), "r"(b1));
}
__device__ __forceinline__ void cp_async16(uint32_t smem_dst, const void* gsrc) {
    asm volatile("cp.async.cg.shared.global [%0], [%1], 16;"
                 :: "r"(smem_dst), "l"(gsrc));
}
#define CP_COMMIT() asm volatile("cp.async.commit_group;" ::: "memory")
#define CP_WAIT0()  asm volatile("cp.async.wait_group 0;"  ::: "memory")

// ---------------------------------------------------------------------------
// Kernel 1: k -> fp16 convert. grid 128, 256 threads.
// ---------------------------------------------------------------------------
__global__ __launch_bounds__(256)
void kconv_kernel(const float* __restrict__ k)
{
    const int t = threadIdx.x;
    const size_t base = (size_t)blockIdx.x * 8192;
    __half2* ph = reinterpret_cast<__half2*>(g_khi);
    #pragma unroll
    for (int it = 0; it < 32; it++) {
        const size_t i = base + (size_t)it * 256 + t;
        float4 v = reinterpret_cast<const float4*>(k)[i];
        ph[2 * i]     = __floats2half2_rn(v.x, v.y);
        ph[2 * i + 1] = __floats2half2_rn(v.z, v.w);
    }
}

// ---------------------------------------------------------------------------
// Kernel 2: 64-row persistent strips, 128 threads, 4 CTAs/SM.
//   Fold prologue: q''(strip) = q @ (32*I + Wd[h]*W[h]) -> smem A (fp16).
//   J-loop: 8 tiles of 64x128, cp.async double-buffered B, direct .cs stores.
// grid (1, 16, 64) = 1024 CTAs.
// SMEM overlays (from 1K-aligned base, 48K total):
//   fold:   Qh[0,8K) Ql[8K,16K) Mh[16K,24K) Ml[24K,32K)  B0[32K,48K)
//   j-loop: B1[0,16K)           A [16K,24K) (overlays Mh) B0[32K,48K)
// ---------------------------------------------------------------------------
#define OFF_QH 0
#define OFF_QL 8192
#define OFF_MH 16384
#define OFF_ML 24576
#define OFF_A  16384
#define OFF_B0 32768
#define OFF_B1 0
#define SC_SMEM (49152 + 1024)

__global__ __launch_bounds__(128, 4)
void score_mma_kernel(const float* __restrict__ q,
                      const float* __restrict__ W,
                      const float* __restrict__ b,
                      const float* __restrict__ Wd,
                      float* __restrict__ out)
{
    extern __shared__ char smem_raw[];
    const uint32_t smem_base = smem_u32(smem_raw);
    const uint32_t base_al   = (smem_base + 1023u) & ~1023u;
    char* tilec = smem_raw + (base_al - smem_base);

    const int t    = threadIdx.x;
    const int wid  = t >> 5;
    const int lane = t & 31;
    const int bh   = blockIdx.z;
    const int h    = bh % HN;
    const int i0   = blockIdx.y * 64;

    const size_t boff = (size_t)bh * SV * DV;
    const __half* kh = g_khi + boff;

    // ---- Prefetch B tile 0 (128 rows x 128B); overlaps fold ----
    // linear mapping: chunk idx -> smem off = idx*16 (swizzled), gmem = idx*8 halfs
    #pragma unroll
    for (int it = 0; it < 8; it++) {
        const int idx = t + it * 128;              // 0..1023
        cp_async16(base_al + OFF_B0 + sw128((uint32_t)idx * 16), kh + (size_t)idx * 8);
    }
    CP_COMMIT();

    // =========================== FOLD PROLOGUE ===========================
    {
        const float* qb = q + boff + (size_t)i0 * DV;
        const float* Wh = W + (size_t)h * DV * DV;
        const float  wd = Wd[h];

        // Build M = 32*I + wd*W, transposed [e][d], fp16 hi/lo, swizzled
        #pragma unroll
        for (int it = 0; it < 32; it++) {
            const int idx = t + it * 128;          // d*64+e
            const int d = idx >> 6, e = idx & 63;
            float val = wd * Wh[idx] + (d == e ? 32.0f : 0.0f);
            __half hi = __float2half(val);
            __half lo = __float2half(val - __half2float(hi));
            const uint32_t off = sw128((uint32_t)(e * 128 + d * 2));
            *reinterpret_cast<__half*>(tilec + OFF_MH + off) = hi;
            *reinterpret_cast<__half*>(tilec + OFF_ML + off) = lo;
        }

        // Load q strip (64x64 f32), split hi/lo into swizzled fp16 tiles
        #pragma unroll
        for (int it = 0; it < 4; it++) {
            const int idx = t + it * 128;          // 0..511
            const float4 v0 = reinterpret_cast<const float4*>(qb)[idx * 2];
            const float4 v1 = reinterpret_cast<const float4*>(qb)[idx * 2 + 1];
            __half h0 = __float2half(v0.x), h1 = __float2half(v0.y);
            __half h2 = __float2half(v0.z), h3 = __float2half(v0.w);
            __half h4 = __float2half(v1.x), h5 = __float2half(v1.y);
            __half h6 = __float2half(v1.z), h7 = __float2half(v1.w);
            __half2 hv[4] = { __half2(h0,h1), __half2(h2,h3), __half2(h4,h5), __half2(h6,h7) };
            __half2 lv[4] = {
                __floats2half2_rn(v0.x - __half2float(h0), v0.y - __half2float(h1)),
                __floats2half2_rn(v0.z - __half2float(h2), v0.w - __half2float(h3)),
                __floats2half2_rn(v1.x - __half2float(h4), v1.y - __half2float(h5)),
                __floats2half2_rn(v1.z - __half2float(h6), v1.w - __half2float(h7)) };
            const uint32_t off = sw128((uint32_t)idx * 16);
            *reinterpret_cast<uint4*>(tilec + OFF_QH + off) = *reinterpret_cast<uint4*>(hv);
            *reinterpret_cast<uint4*>(tilec + OFF_QL + off) = *reinterpret_cast<uint4*>(lv);
        }
        __syncthreads();

        // fold MMA: warp grid 2M x 2N (warp tile 32x32) over 64x64
        const int m0w = (wid & 1) * 32;
        const int n0w = (wid >> 1) * 32;

        float acc[2][4][4];
        #pragma unroll
        for (int m = 0; m < 2; m++)
            #pragma unroll
            for (int n = 0; n < 4; n++)
                #pragma unroll
                for (int r = 0; r < 4; r++) acc[m][n][r] = 0.0f;

        const uint32_t a_row = lane & 15;
        const uint32_t a_ch  = (lane >> 4) << 4;
        const uint32_t b_row = (lane & 7) | ((lane >> 4) << 3);
        const uint32_t b_ch  = ((lane >> 3) & 1) << 4;

        #pragma unroll
        for (int kk = 0; kk < 4; kk++) {
            const uint32_t kb = (uint32_t)kk * 32;
            uint32_t ah[2][4], al[2][4];
            #pragma unroll
            for (int m = 0; m < 2; m++) {
                const uint32_t ro = sw128((uint32_t)(m0w + m * 16 + a_row) * 128 + kb + a_ch);
                ldsm_x4(base_al + OFF_QH + ro, ah[m][0], ah[m][1], ah[m][2], ah[m][3]);
                ldsm_x4(base_al + OFF_QL + ro, al[m][0], al[m][1], al[m][2], al[m][3]);
            }
            uint32_t bh_f[4][2], bl_f[4][2];
            #pragma unroll
            for (int tn = 0; tn < 2; tn++) {
                const uint32_t ro = sw128((uint32_t)(n0w + tn * 16 + b_row) * 128 + kb + b_ch);
                ldsm_x4(base_al + OFF_MH + ro, bh_f[2*tn][0], bh_f[2*tn][1], bh_f[2*tn+1][0], bh_f[2*tn+1][1]);
                ldsm_x4(base_al + OFF_ML + ro, bl_f[2*tn][0], bl_f[2*tn][1], bl_f[2*tn+1][0], bl_f[2*tn+1][1]);
            }
            #pragma unroll
            for (int m = 0; m < 2; m++)
                #pragma unroll
                for (int n = 0; n < 4; n++) {
                    mma_f16(acc[m][n], ah[m], bh_f[n][0], bh_f[n][1]);
                    mma_f16(acc[m][n], ah[m], bl_f[n][0], bl_f[n][1]);
                    mma_f16(acc[m][n], al[m], bh_f[n][0], bh_f[n][1]);
                }
        }
        __syncthreads();   // all Q/M reads done before A overlays Mh

        // Write q'' tile to smem A (fp16, SW128)
        #pragma unroll
        for (int m = 0; m < 2; m++) {
            #pragma unroll
            for (int half = 0; half < 2; half++) {
                const int row = m0w + m * 16 + half * 8 + (lane >> 2);
                #pragma unroll
                for (int n = 0; n < 4; n++) {
                    const int col = n0w + n * 8 + (lane & 3) * 2;
                    __half2 v = __floats2half2_rn(acc[m][n][half * 2], acc[m][n][half * 2 + 1]);
                    const uint32_t off = sw128((uint32_t)(row * 128 + col * 2));
                    *reinterpret_cast<__half2*>(tilec + OFF_A + off) = v;
                }
            }
        }
    }

    CP_WAIT0();          // B0 resident
    __syncthreads();     // A visible; Qh/Ql region now dead -> B1

    // ============================ J-LOOP ============================
    const int m0wj = (wid & 1) * 32;
    const int n0wj = (wid >> 1) * 64;

    const uint32_t a_row = lane & 15;
    const uint32_t a_ch  = (lane >> 4) << 4;
    const uint32_t b_row = (lane & 7) | ((lane >> 4) << 3);
    const uint32_t b_ch  = ((lane >> 3) & 1) << 4;

    const float cbias = Wd[h] * b[h];
    float* obase = out + (size_t)bh * SV * SV;

    for (int jt = 0; jt < 8; jt++) {
        const uint32_t Bb = base_al + ((jt & 1) ? OFF_B1 : OFF_B0);

        // prefetch next B tile into the other buffer
        if (jt < 7) {
            const __half* kn = kh + (size_t)(jt + 1) * 128 * DV;
            const uint32_t Bn = base_al + ((jt & 1) ? OFF_B0 : OFF_B1);
            #pragma unroll
            for (int it = 0; it < 8; it++) {
                const int idx = t + it * 128;
                cp_async16(Bn + sw128((uint32_t)idx * 16), kn + (size_t)idx * 8);
            }
            CP_COMMIT();
        }

        // ---- compute 64x128 tile (warp tile 32x64) ----
        float acc[2][8][4];
        #pragma unroll
        for (int m = 0; m < 2; m++)
            #pragma unroll
            for (int n = 0; n < 8; n++)
                #pragma unroll
                for (int r = 0; r < 4; r++) acc[m][n][r] = 0.0f;

        #pragma unroll
        for (int kk = 0; kk < 4; kk++) {
            const uint32_t kb = (uint32_t)kk * 32;
            uint32_t a[2][4];
            #pragma unroll
            for (int m = 0; m < 2; m++) {
                const uint32_t ro = sw128((uint32_t)(m0wj + m * 16 + a_row) * 128 + kb + a_ch);
                ldsm_x4(base_al + OFF_A + ro, a[m][0], a[m][1], a[m][2], a[m][3]);
            }
            uint32_t bf[8][2];
            #pragma unroll
            for (int tn = 0; tn < 4; tn++) {
                const uint32_t ro = sw128((uint32_t)(n0wj + tn * 16 + b_row) * 128 + kb + b_ch);
                ldsm_x4(Bb + ro, bf[2*tn][0], bf[2*tn][1], bf[2*tn+1][0], bf[2*tn+1][1]);
            }
            #pragma unroll
            for (int m = 0; m < 2; m++)
                #pragma unroll
                for (int n = 0; n < 8; n++)
                    mma_f16(acc[m][n], a[m], bf[n][0], bf[n][1]);
        }

        // ---- direct streaming-store epilogue ----
        const int row_base = i0 + m0wj + (lane >> 2);
        const int col_base = jt * 128 + n0wj + (lane & 3) * 2;
        #pragma unroll
        for (int m = 0; m < 2; m++) {
            #pragma unroll
            for (int half = 0; half < 2; half++) {
                const int r = row_base + m * 16 + half * 8;
                float* prow = obase + (size_t)r * SV + col_base;
                #pragma unroll
                for (int n = 0; n < 8; n++) {
                    asm volatile("st.global.cs.v2.f32 [%0], {%1, %2};"
                                 :: "l"(prow + n * 8),
                                    "f"(acc[m][n][half * 2 + 0] + cbias),
                                    "f"(acc[m][n][half * 2 + 1] + cbias) : "memory");
                }
            }
        }

        if (jt < 7) {
            CP_WAIT0();
            __syncthreads();
        }
    }
}

// ---------------------------------------------------------------------------
extern "C" void kernel_launch(void* const* d_in, const int* in_sizes, int n_in,
                              void* d_out, int out_size)
{
    const float* q  = (const float*)d_in[0];
    const float* k  = (const float*)d_in[1];
    const float* W  = (const float*)d_in[2];
    const float* b  = (const float*)d_in[3];
    const float* Wd = (const float*)d_in[4];
    float* out = (float*)d_out;

    cudaFuncSetAttribute(score_mma_kernel,
                         cudaFuncAttributeMaxDynamicSharedMemorySize, SC_SMEM);

    kconv_kernel<<<128, 256>>>(k);

    dim3 g3(1, SV / 64, BH);
    score_mma_kernel<<<g3, 128, SC_SMEM>>>(q, W, b, Wd, out);
}

// round 12
// speedup vs baseline: 1.5074x; 1.0841x over previous
#include <cuda_runtime.h>
#include <cuda_fp16.h>
#include <cstdint>
#include <cstddef>

// Problem constants
#define BV 4
#define HN 16
#define SV 1024
#define DV 64
#define BH (BV*HN)

// fp16 k operand (device scratch; no allocation)
__device__ __half g_khi[(size_t)BH * SV * DV];

__device__ __forceinline__ uint32_t smem_u32(const void* p) {
    uint32_t a;
    asm("{ .reg .u64 t; cvta.to.shared.u64 t, %1; cvt.u32.u64 %0, t; }" : "=r"(a) : "l"(p));
    return a;
}
__device__ __forceinline__ uint32_t sw128(uint32_t off) {
    return off ^ ((off >> 3) & 0x70);
}
__device__ __forceinline__ void ldsm_x4(uint32_t addr, uint32_t& r0, uint32_t& r1,
                                        uint32_t& r2, uint32_t& r3) {
    asm volatile("ldmatrix.sync.aligned.m8n8.x4.shared.b16 {%0,%1,%2,%3}, [%4];"
                 : "=r"(r0), "=r"(r1), "=r"(r2), "=r"(r3) : "r"(addr));
}
__device__ __forceinline__ void mma_f16(float* c, const uint32_t* a,
                                        uint32_t b0, uint32_t b1) {
    asm volatile(
        "mma.sync.aligned.m16n8k16.row.col.f32.f16.f16.f32 "
        "{%0,%1,%2,%3}, {%4,%5,%6,%7}, {%8,%9}, {%0,%1,%2,%3};"
        : "+f"(c[0]), "+f"(c[1]), "+f"(c[2]), "+f"(c[3])
        : "r"(a[0]), "r"(a[1]), "r"(a[2]), "r"(a[3]), "r"(b0), "r"(b1));
}
__device__ __forceinline__ void cp_async16(uint32_t smem_dst, const void* gsrc) {
    asm volatile("cp.async.cg.shared.global [%0], [%1], 16;"
                 :: "r"(smem_dst), "l"(gsrc));
}
#define CP_COMMIT() asm volatile("cp.async.commit_group;" ::: "memory")
#define CP_WAIT0()  asm volatile("cp.async.wait_group 0;"  ::: "memory")

// ---------------------------------------------------------------------------
// Kernel 1: k -> fp16 convert. grid 128, 256 threads.
// ---------------------------------------------------------------------------
__global__ __launch_bounds__(256)
void kconv_kernel(const float* __restrict__ k)
{
    const int t = threadIdx.x;
    const size_t base = (size_t)blockIdx.x * 8192;
    __half2* ph = reinterpret_cast<__half2*>(g_khi);
    #pragma unroll
    for (int it = 0; it < 32; it++) {
        const size_t i = base + (size_t)it * 256 + t;
        float4 v = reinterpret_cast<const float4*>(k)[i];
        ph[2 * i]     = __floats2half2_rn(v.x, v.y);
        ph[2 * i + 1] = __floats2half2_rn(v.z, v.w);
    }
}

// ---------------------------------------------------------------------------
// Kernel 2: 64-row persistent strips, 128 threads, 4 CTAs/SM.
//   Fold prologue: q''(strip) = q @ (32*I + Wd[h]*W[h]) -> smem A (fp16).
//   J-loop: 8 tiles of 64x128, cp.async double-buffered B,
//           shuffle-widened STG.128 streaming stores.
// grid (1, 16, 64) = 1024 CTAs.
// SMEM overlays (from 1K-aligned base, 48K total):
//   fold:   Qh[0,8K) Ql[8K,16K) Mh[16K,24K) Ml[24K,32K)  B0[32K,48K)
//   j-loop: B1[0,16K)           A [16K,24K) (overlays Mh) B0[32K,48K)
// ---------------------------------------------------------------------------
#define OFF_QH 0
#define OFF_QL 8192
#define OFF_MH 16384
#define OFF_ML 24576
#define OFF_A  16384
#define OFF_B0 32768
#define OFF_B1 0
#define SC_SMEM (49152 + 1024)

__global__ __launch_bounds__(128, 4)
void score_mma_kernel(const float* __restrict__ q,
                      const float* __restrict__ W,
                      const float* __restrict__ b,
                      const float* __restrict__ Wd,
                      float* __restrict__ out)
{
    extern __shared__ char smem_raw[];
    const uint32_t smem_base = smem_u32(smem_raw);
    const uint32_t base_al   = (smem_base + 1023u) & ~1023u;
    char* tilec = smem_raw + (base_al - smem_base);

    const int t    = threadIdx.x;
    const int wid  = t >> 5;
    const int lane = t & 31;
    const int bh   = blockIdx.z;
    const int h    = bh % HN;
    const int i0   = blockIdx.y * 64;

    const size_t boff = (size_t)bh * SV * DV;
    const __half* kh = g_khi + boff;

    // ---- Prefetch B tile 0 (128 rows x 128B); overlaps fold ----
    #pragma unroll
    for (int it = 0; it < 8; it++) {
        const int idx = t + it * 128;              // 0..1023
        cp_async16(base_al + OFF_B0 + sw128((uint32_t)idx * 16), kh + (size_t)idx * 8);
    }
    CP_COMMIT();

    // =========================== FOLD PROLOGUE ===========================
    {
        const float* qb = q + boff + (size_t)i0 * DV;
        const float* Wh = W + (size_t)h * DV * DV;
        const float  wd = Wd[h];

        // Build M = 32*I + wd*W, transposed [e][d], fp16 hi/lo, swizzled
        #pragma unroll
        for (int it = 0; it < 32; it++) {
            const int idx = t + it * 128;          // d*64+e
            const int d = idx >> 6, e = idx & 63;
            float val = wd * Wh[idx] + (d == e ? 32.0f : 0.0f);
            __half hi = __float2half(val);
            __half lo = __float2half(val - __half2float(hi));
            const uint32_t off = sw128((uint32_t)(e * 128 + d * 2));
            *reinterpret_cast<__half*>(tilec + OFF_MH + off) = hi;
            *reinterpret_cast<__half*>(tilec + OFF_ML + off) = lo;
        }

        // Load q strip (64x64 f32), split hi/lo into swizzled fp16 tiles
        #pragma unroll
        for (int it = 0; it < 4; it++) {
            const int idx = t + it * 128;          // 0..511
            const float4 v0 = reinterpret_cast<const float4*>(qb)[idx * 2];
            const float4 v1 = reinterpret_cast<const float4*>(qb)[idx * 2 + 1];
            __half h0 = __float2half(v0.x), h1 = __float2half(v0.y);
            __half h2 = __float2half(v0.z), h3 = __float2half(v0.w);
            __half h4 = __float2half(v1.x), h5 = __float2half(v1.y);
            __half h6 = __float2half(v1.z), h7 = __float2half(v1.w);
            __half2 hv[4] = { __half2(h0,h1), __half2(h2,h3), __half2(h4,h5), __half2(h6,h7) };
            __half2 lv[4] = {
                __floats2half2_rn(v0.x - __half2float(h0), v0.y - __half2float(h1)),
                __floats2half2_rn(v0.z - __half2float(h2), v0.w - __half2float(h3)),
                __floats2half2_rn(v1.x - __half2float(h4), v1.y - __half2float(h5)),
                __floats2half2_rn(v1.z - __half2float(h6), v1.w - __half2float(h7)) };
            const uint32_t off = sw128((uint32_t)idx * 16);
            *reinterpret_cast<uint4*>(tilec + OFF_QH + off) = *reinterpret_cast<uint4*>(hv);
            *reinterpret_cast<uint4*>(tilec + OFF_QL + off) = *reinterpret_cast<uint4*>(lv);
        }
        __syncthreads();

        // fold MMA: warp grid 2M x 2N (warp tile 32x32) over 64x64
        const int m0w = (wid & 1) * 32;
        const int n0w = (wid >> 1) * 32;

        float acc[2][4][4];
        #pragma unroll
        for (int m = 0; m < 2; m++)
            #pragma unroll
            for (int n = 0; n < 4; n++)
                #pragma unroll
                for (int r = 0; r < 4; r++) acc[m][n][r] = 0.0f;

        const uint32_t a_row = lane & 15;
        const uint32_t a_ch  = (lane >> 4) << 4;
        const uint32_t b_row = (lane & 7) | ((lane >> 4) << 3);
        const uint32_t b_ch  = ((lane >> 3) & 1) << 4;

        #pragma unroll
        for (int kk = 0; kk < 4; kk++) {
            const uint32_t kb = (uint32_t)kk * 32;
            uint32_t ah[2][4], al[2][4];
            #pragma unroll
            for (int m = 0; m < 2; m++) {
                const uint32_t ro = sw128((uint32_t)(m0w + m * 16 + a_row) * 128 + kb + a_ch);
                ldsm_x4(base_al + OFF_QH + ro, ah[m][0], ah[m][1], ah[m][2], ah[m][3]);
                ldsm_x4(base_al + OFF_QL + ro, al[m][0], al[m][1], al[m][2], al[m][3]);
            }
            uint32_t bh_f[4][2], bl_f[4][2];
            #pragma unroll
            for (int tn = 0; tn < 2; tn++) {
                const uint32_t ro = sw128((uint32_t)(n0w + tn * 16 + b_row) * 128 + kb + b_ch);
                ldsm_x4(base_al + OFF_MH + ro, bh_f[2*tn][0], bh_f[2*tn][1], bh_f[2*tn+1][0], bh_f[2*tn+1][1]);
                ldsm_x4(base_al + OFF_ML + ro, bl_f[2*tn][0], bl_f[2*tn][1], bl_f[2*tn+1][0], bl_f[2*tn+1][1]);
            }
            #pragma unroll
            for (int m = 0; m < 2; m++)
                #pragma unroll
                for (int n = 0; n < 4; n++) {
                    mma_f16(acc[m][n], ah[m], bh_f[n][0], bh_f[n][1]);
                    mma_f16(acc[m][n], ah[m], bl_f[n][0], bl_f[n][1]);
                    mma_f16(acc[m][n], al[m], bh_f[n][0], bh_f[n][1]);
                }
        }
        __syncthreads();   // all Q/M reads done before A overlays Mh

        // Write q'' tile to smem A (fp16, SW128)
        #pragma unroll
        for (int m = 0; m < 2; m++) {
            #pragma unroll
            for (int half = 0; half < 2; half++) {
                const int row = m0w + m * 16 + half * 8 + (lane >> 2);
                #pragma unroll
                for (int n = 0; n < 4; n++) {
                    const int col = n0w + n * 8 + (lane & 3) * 2;
                    __half2 v = __floats2half2_rn(acc[m][n][half * 2], acc[m][n][half * 2 + 1]);
                    const uint32_t off = sw128((uint32_t)(row * 128 + col * 2));
                    *reinterpret_cast<__half2*>(tilec + OFF_A + off) = v;
                }
            }
        }
    }

    CP_WAIT0();          // B0 resident
    __syncthreads();     // A visible; Qh/Ql region now dead -> B1

    // ============================ J-LOOP ============================
    const int m0wj = (wid & 1) * 32;
    const int n0wj = (wid >> 1) * 64;

    const uint32_t a_row = lane & 15;
    const uint32_t a_ch  = (lane >> 4) << 4;
    const uint32_t b_row = (lane & 7) | ((lane >> 4) << 3);
    const uint32_t b_ch  = ((lane >> 3) & 1) << 4;

    const float cbias = Wd[h] * b[h];
    float* obase = out + (size_t)bh * SV * SV;

    const int l3   = lane & 3;
    const int sel  = l3 & 1;            // 0: assemble even fragment, 1: odd
    const int coff = (l3 >> 1) * 4;     // 0 or 4 within the 8-col fragment

    for (int jt = 0; jt < 8; jt++) {
        const uint32_t Bb = base_al + ((jt & 1) ? OFF_B1 : OFF_B0);

        // prefetch next B tile into the other buffer
        if (jt < 7) {
            const __half* kn = kh + (size_t)(jt + 1) * 128 * DV;
            const uint32_t Bn = base_al + ((jt & 1) ? OFF_B0 : OFF_B1);
            #pragma unroll
            for (int it = 0; it < 8; it++) {
                const int idx = t + it * 128;
                cp_async16(Bn + sw128((uint32_t)idx * 16), kn + (size_t)idx * 8);
            }
            CP_COMMIT();
        }

        // ---- compute 64x128 tile (warp tile 32x64) ----
        float acc[2][8][4];
        #pragma unroll
        for (int m = 0; m < 2; m++)
            #pragma unroll
            for (int n = 0; n < 8; n++)
                #pragma unroll
                for (int r = 0; r < 4; r++) acc[m][n][r] = 0.0f;

        #pragma unroll
        for (int kk = 0; kk < 4; kk++) {
            const uint32_t kb = (uint32_t)kk * 32;
            uint32_t a[2][4];
            #pragma unroll
            for (int m = 0; m < 2; m++) {
                const uint32_t ro = sw128((uint32_t)(m0wj + m * 16 + a_row) * 128 + kb + a_ch);
                ldsm_x4(base_al + OFF_A + ro, a[m][0], a[m][1], a[m][2], a[m][3]);
            }
            uint32_t bf[8][2];
            #pragma unroll
            for (int tn = 0; tn < 4; tn++) {
                const uint32_t ro = sw128((uint32_t)(n0wj + tn * 16 + b_row) * 128 + kb + b_ch);
                ldsm_x4(Bb + ro, bf[2*tn][0], bf[2*tn][1], bf[2*tn+1][0], bf[2*tn+1][1]);
            }
            #pragma unroll
            for (int m = 0; m < 2; m++)
                #pragma unroll
                for (int n = 0; n < 8; n++)
                    mma_f16(acc[m][n], a[m], bf[n][0], bf[n][1]);
        }

        // ---- shuffle-widened streaming-store epilogue (STG.128) ----
        // Lane pair (xor 1) exchanges other-parity fragment halves so each
        // lane stores 4 contiguous floats: 16 contiguous floats per row per
        // instruction -> 64B wavefronts instead of 32B.
        #pragma unroll
        for (int m = 0; m < 2; m++) {
            #pragma unroll
            for (int half = 0; half < 2; half++) {
                const int r = i0 + m0wj + m * 16 + half * 8 + (lane >> 2);
                float* prow = obase + (size_t)r * SV + jt * 128 + n0wj;
                #pragma unroll
                for (int i2 = 0; i2 < 4; i2++) {
                    const float e0 = acc[m][2*i2][half*2+0] + cbias;
                    const float e1 = acc[m][2*i2][half*2+1] + cbias;
                    const float o0 = acc[m][2*i2+1][half*2+0] + cbias;
                    const float o1 = acc[m][2*i2+1][half*2+1] + cbias;
                    // contribute other-parity fragment, keep own-parity
                    const float cx = sel ? e0 : o0;
                    const float cy = sel ? e1 : o1;
                    const float ax = sel ? o0 : e0;
                    const float ay = sel ? o1 : e1;
                    const float rx = __shfl_xor_sync(0xffffffffu, cx, 1);
                    const float ry = __shfl_xor_sync(0xffffffffu, cy, 1);
                    const float v0 = sel ? rx : ax;
                    const float v1 = sel ? ry : ay;
                    const float v2 = sel ? ax : rx;
                    const float v3 = sel ? ay : ry;
                    asm volatile("st.global.cs.v4.f32 [%0], {%1,%2,%3,%4};"
                                 :: "l"(prow + i2 * 16 + sel * 8 + coff),
                                    "f"(v0), "f"(v1), "f"(v2), "f"(v3) : "memory");
                }
            }
        }

        if (jt < 7) {
            CP_WAIT0();
            __syncthreads();
        }
    }
}

// ---------------------------------------------------------------------------
extern "C" void kernel_launch(void* const* d_in, const int* in_sizes, int n_in,
                              void* d_out, int out_size)
{
    const float* q  = (const float*)d_in[0];
    const float* k  = (const float*)d_in[1];
    const float* W  = (const float*)d_in[2];
    const float* b  = (const float*)d_in[3];
    const float* Wd = (const float*)d_in[4];
    float* out = (float*)d_out;

    cudaFuncSetAttribute(score_mma_kernel,
                         cudaFuncAttributeMaxDynamicSharedMemorySize, SC_SMEM);

    kconv_kernel<<<128, 256>>>(k);

    dim3 g3(1, SV / 64, BH);
    score_mma_kernel<<<g3, 128, SC_SMEM>>>(q, W, b, Wd, out);
}

// round 13
// speedup vs baseline: 1.5565x; 1.0326x over previous
#include <cuda_runtime.h>
#include <cuda_fp16.h>
#include <cstdint>
#include <cstddef>

// Problem constants
#define BV 4
#define HN 16
#define SV 1024
#define DV 64
#define BH (BV*HN)

// fp16 k operand (device scratch; no allocation)
__device__ __half g_khi[(size_t)BH * SV * DV];
// monotonic per-bh arrival counters (zero-initialized once at module load;
// ticket scheme never needs a reset -> graph-replay safe)
__device__ unsigned g_cnt[BH];

__device__ __forceinline__ uint32_t smem_u32(const void* p) {
    uint32_t a;
    asm("{ .reg .u64 t; cvta.to.shared.u64 t, %1; cvt.u32.u64 %0, t; }" : "=r"(a) : "l"(p));
    return a;
}
__device__ __forceinline__ uint32_t sw128(uint32_t off) {
    return off ^ ((off >> 3) & 0x70);
}
__device__ __forceinline__ void ldsm_x4(uint32_t addr, uint32_t& r0, uint32_t& r1,
                                        uint32_t& r2, uint32_t& r3) {
    asm volatile("ldmatrix.sync.aligned.m8n8.x4.shared.b16 {%0,%1,%2,%3}, [%4];"
                 : "=r"(r0), "=r"(r1), "=r"(r2), "=r"(r3) : "r"(addr));
}
__device__ __forceinline__ void mma_f16(float* c, const uint32_t* a,
                                        uint32_t b0, uint32_t b1) {
    asm volatile(
        "mma.sync.aligned.m16n8k16.row.col.f32.f16.f16.f32 "
        "{%0,%1,%2,%3}, {%4,%5,%6,%7}, {%8,%9}, {%0,%1,%2,%3};"
        : "+f"(c[0]), "+f"(c[1]), "+f"(c[2]), "+f"(c[3])
        : "r"(a[0]), "r"(a[1]), "r"(a[2]), "r"(a[3]), "r"(b0), "r"(b1));
}
__device__ __forceinline__ void cp_async16(uint32_t smem_dst, const void* gsrc) {
    asm volatile("cp.async.cg.shared.global [%0], [%1], 16;"
                 :: "r"(smem_dst), "l"(gsrc));
}
#define CP_COMMIT() asm volatile("cp.async.commit_group;" ::: "memory")
#define CP_WAIT0()  asm volatile("cp.async.wait_group 0;"  ::: "memory")

// ---------------------------------------------------------------------------
// Single fused kernel: k-slice convert + ticket barrier + fold prologue +
// persistent 64-row strip GEMM with double-buffered cp.async B and
// shuffle-widened STG.128 streaming stores.
// grid (1, 16, 64) = 1024 CTAs, 128 threads, 4 CTAs/SM.
// SMEM overlays (from 1K-aligned base, 48K total):
//   fold:   Qh[0,8K) Ql[8K,16K) Mh[16K,24K) Ml[24K,32K)  B0[32K,48K)
//   j-loop: B1[0,16K)           A [16K,24K) (overlays Mh) B0[32K,48K)
// ---------------------------------------------------------------------------
#define OFF_QH 0
#define OFF_QL 8192
#define OFF_MH 16384
#define OFF_ML 24576
#define OFF_A  16384
#define OFF_B0 32768
#define OFF_B1 0
#define SC_SMEM (49152 + 1024)

__global__ __launch_bounds__(128, 4)
void score_mma_kernel(const float* __restrict__ q,
                      const float* __restrict__ kf,
                      const float* __restrict__ W,
                      const float* __restrict__ b,
                      const float* __restrict__ Wd,
                      float* __restrict__ out)
{
    extern __shared__ char smem_raw[];
    const uint32_t smem_base = smem_u32(smem_raw);
    const uint32_t base_al   = (smem_base + 1023u) & ~1023u;
    char* tilec = smem_raw + (base_al - smem_base);

    const int t    = threadIdx.x;
    const int wid  = t >> 5;
    const int lane = t & 31;
    const int bh   = blockIdx.z;
    const int h    = bh % HN;
    const int i0   = blockIdx.y * 64;

    const size_t boff = (size_t)bh * SV * DV;
    const __half* kh = g_khi + boff;

    // ================= K-SLICE CONVERT (own 64 rows) =================
    {
        const float* ks = kf + boff + (size_t)i0 * DV;
        __half2* kd = reinterpret_cast<__half2*>(g_khi + boff + (size_t)i0 * DV);
        #pragma unroll
        for (int it = 0; it < 8; it++) {
            const int idx = t + it * 128;          // 0..1023 float4s
            float4 v = reinterpret_cast<const float4*>(ks)[idx];
            kd[2 * idx]     = __floats2half2_rn(v.x, v.y);
            kd[2 * idx + 1] = __floats2half2_rn(v.z, v.w);
        }
    }
    __threadfence();
    __syncthreads();
    unsigned target = 0;
    if (t == 0) {
        unsigned my = atomicAdd(&g_cnt[bh], 1u);
        target = (my / 16u + 1u) * 16u;
    }

    // =========================== FOLD PROLOGUE ===========================
    // (independent of k -> overlaps peer CTAs' conversions)
    {
        const float* qb = q + boff + (size_t)i0 * DV;
        const float* Wh = W + (size_t)h * DV * DV;
        const float  wd = Wd[h];

        // Build M = 32*I + wd*W, transposed [e][d], fp16 hi/lo, swizzled
        #pragma unroll
        for (int it = 0; it < 32; it++) {
            const int idx = t + it * 128;          // d*64+e
            const int d = idx >> 6, e = idx & 63;
            float val = wd * Wh[idx] + (d == e ? 32.0f : 0.0f);
            __half hi = __float2half(val);
            __half lo = __float2half(val - __half2float(hi));
            const uint32_t off = sw128((uint32_t)(e * 128 + d * 2));
            *reinterpret_cast<__half*>(tilec + OFF_MH + off) = hi;
            *reinterpret_cast<__half*>(tilec + OFF_ML + off) = lo;
        }

        // Load q strip (64x64 f32), split hi/lo into swizzled fp16 tiles
        #pragma unroll
        for (int it = 0; it < 4; it++) {
            const int idx = t + it * 128;          // 0..511
            const float4 v0 = reinterpret_cast<const float4*>(qb)[idx * 2];
            const float4 v1 = reinterpret_cast<const float4*>(qb)[idx * 2 + 1];
            __half h0 = __float2half(v0.x), h1 = __float2half(v0.y);
            __half h2 = __float2half(v0.z), h3 = __float2half(v0.w);
            __half h4 = __float2half(v1.x), h5 = __float2half(v1.y);
            __half h6 = __float2half(v1.z), h7 = __float2half(v1.w);
            __half2 hv[4] = { __half2(h0,h1), __half2(h2,h3), __half2(h4,h5), __half2(h6,h7) };
            __half2 lv[4] = {
                __floats2half2_rn(v0.x - __half2float(h0), v0.y - __half2float(h1)),
                __floats2half2_rn(v0.z - __half2float(h2), v0.w - __half2float(h3)),
                __floats2half2_rn(v1.x - __half2float(h4), v1.y - __half2float(h5)),
                __floats2half2_rn(v1.z - __half2float(h6), v1.w - __half2float(h7)) };
            const uint32_t off = sw128((uint32_t)idx * 16);
            *reinterpret_cast<uint4*>(tilec + OFF_QH + off) = *reinterpret_cast<uint4*>(hv);
            *reinterpret_cast<uint4*>(tilec + OFF_QL + off) = *reinterpret_cast<uint4*>(lv);
        }
        __syncthreads();

        // fold MMA: warp grid 2M x 2N (warp tile 32x32) over 64x64
        const int m0w = (wid & 1) * 32;
        const int n0w = (wid >> 1) * 32;

        float acc[2][4][4];
        #pragma unroll
        for (int m = 0; m < 2; m++)
            #pragma unroll
            for (int n = 0; n < 4; n++)
                #pragma unroll
                for (int r = 0; r < 4; r++) acc[m][n][r] = 0.0f;

        const uint32_t a_row = lane & 15;
        const uint32_t a_ch  = (lane >> 4) << 4;
        const uint32_t b_row = (lane & 7) | ((lane >> 4) << 3);
        const uint32_t b_ch  = ((lane >> 3) & 1) << 4;

        #pragma unroll
        for (int kk = 0; kk < 4; kk++) {
            const uint32_t kb = (uint32_t)kk * 32;
            uint32_t ah[2][4], al[2][4];
            #pragma unroll
            for (int m = 0; m < 2; m++) {
                const uint32_t ro = sw128((uint32_t)(m0w + m * 16 + a_row) * 128 + kb + a_ch);
                ldsm_x4(base_al + OFF_QH + ro, ah[m][0], ah[m][1], ah[m][2], ah[m][3]);
                ldsm_x4(base_al + OFF_QL + ro, al[m][0], al[m][1], al[m][2], al[m][3]);
            }
            uint32_t bh_f[4][2], bl_f[4][2];
            #pragma unroll
            for (int tn = 0; tn < 2; tn++) {
                const uint32_t ro = sw128((uint32_t)(n0w + tn * 16 + b_row) * 128 + kb + b_ch);
                ldsm_x4(base_al + OFF_MH + ro, bh_f[2*tn][0], bh_f[2*tn][1], bh_f[2*tn+1][0], bh_f[2*tn+1][1]);
                ldsm_x4(base_al + OFF_ML + ro, bl_f[2*tn][0], bl_f[2*tn][1], bl_f[2*tn+1][0], bl_f[2*tn+1][1]);
            }
            #pragma unroll
            for (int m = 0; m < 2; m++)
                #pragma unroll
                for (int n = 0; n < 4; n++) {
                    mma_f16(acc[m][n], ah[m], bh_f[n][0], bh_f[n][1]);
                    mma_f16(acc[m][n], ah[m], bl_f[n][0], bl_f[n][1]);
                    mma_f16(acc[m][n], al[m], bh_f[n][0], bh_f[n][1]);
                }
        }
        __syncthreads();   // all Q/M reads done before A overlays Mh

        // Write q'' tile to smem A (fp16, SW128)
        #pragma unroll
        for (int m = 0; m < 2; m++) {
            #pragma unroll
            for (int half = 0; half < 2; half++) {
                const int row = m0w + m * 16 + half * 8 + (lane >> 2);
                #pragma unroll
                for (int n = 0; n < 4; n++) {
                    const int col = n0w + n * 8 + (lane & 3) * 2;
                    __half2 v = __floats2half2_rn(acc[m][n][half * 2], acc[m][n][half * 2 + 1]);
                    const uint32_t off = sw128((uint32_t)(row * 128 + col * 2));
                    *reinterpret_cast<__half2*>(tilec + OFF_A + off) = v;
                }
            }
        }
    }

    // ================= TICKET BARRIER: wait for all 16 peers =================
    if (t == 0) {
        while (atomicAdd(&g_cnt[bh], 0u) < target) __nanosleep(64);
        __threadfence();
    }
    __syncthreads();     // A visible to all; peers' k conversions visible

    // ---- Prefetch B tile 0 (128 rows x 128B) ----
    #pragma unroll
    for (int it = 0; it < 8; it++) {
        const int idx = t + it * 128;              // 0..1023
        cp_async16(base_al + OFF_B0 + sw128((uint32_t)idx * 16), kh + (size_t)idx * 8);
    }
    CP_COMMIT();
    CP_WAIT0();
    __syncthreads();

    // ============================ J-LOOP ============================
    const int m0wj = (wid & 1) * 32;
    const int n0wj = (wid >> 1) * 64;

    const uint32_t a_row = lane & 15;
    const uint32_t a_ch  = (lane >> 4) << 4;
    const uint32_t b_row = (lane & 7) | ((lane >> 4) << 3);
    const uint32_t b_ch  = ((lane >> 3) & 1) << 4;

    const float cbias = Wd[h] * b[h];
    float* obase = out + (size_t)bh * SV * SV;

    const int l3   = lane & 3;
    const int sel  = l3 & 1;            // 0: assemble even fragment, 1: odd
    const int coff = (l3 >> 1) * 4;     // 0 or 4 within the 8-col fragment

    for (int jt = 0; jt < 8; jt++) {
        const uint32_t Bb = base_al + ((jt & 1) ? OFF_B1 : OFF_B0);

        // prefetch next B tile into the other buffer
        if (jt < 7) {
            const __half* kn = kh + (size_t)(jt + 1) * 128 * DV;
            const uint32_t Bn = base_al + ((jt & 1) ? OFF_B0 : OFF_B1);
            #pragma unroll
            for (int it = 0; it < 8; it++) {
                const int idx = t + it * 128;
                cp_async16(Bn + sw128((uint32_t)idx * 16), kn + (size_t)idx * 8);
            }
            CP_COMMIT();
        }

        // ---- compute 64x128 tile (warp tile 32x64) ----
        float acc[2][8][4];
        #pragma unroll
        for (int m = 0; m < 2; m++)
            #pragma unroll
            for (int n = 0; n < 8; n++)
                #pragma unroll
                for (int r = 0; r < 4; r++) acc[m][n][r] = 0.0f;

        #pragma unroll
        for (int kk = 0; kk < 4; kk++) {
            const uint32_t kb = (uint32_t)kk * 32;
            uint32_t a[2][4];
            #pragma unroll
            for (int m = 0; m < 2; m++) {
                const uint32_t ro = sw128((uint32_t)(m0wj + m * 16 + a_row) * 128 + kb + a_ch);
                ldsm_x4(base_al + OFF_A + ro, a[m][0], a[m][1], a[m][2], a[m][3]);
            }
            uint32_t bf[8][2];
            #pragma unroll
            for (int tn = 0; tn < 4; tn++) {
                const uint32_t ro = sw128((uint32_t)(n0wj + tn * 16 + b_row) * 128 + kb + b_ch);
                ldsm_x4(Bb + ro, bf[2*tn][0], bf[2*tn][1], bf[2*tn+1][0], bf[2*tn+1][1]);
            }
            #pragma unroll
            for (int m = 0; m < 2; m++)
                #pragma unroll
                for (int n = 0; n < 8; n++)
                    mma_f16(acc[m][n], a[m], bf[n][0], bf[n][1]);
        }

        // ---- shuffle-widened streaming-store epilogue (STG.128) ----
        #pragma unroll
        for (int m = 0; m < 2; m++) {
            #pragma unroll
            for (int half = 0; half < 2; half++) {
                const int r = i0 + m0wj + m * 16 + half * 8 + (lane >> 2);
                float* prow = obase + (size_t)r * SV + jt * 128 + n0wj;
                #pragma unroll
                for (int i2 = 0; i2 < 4; i2++) {
                    const float e0 = acc[m][2*i2][half*2+0] + cbias;
                    const float e1 = acc[m][2*i2][half*2+1] + cbias;
                    const float o0 = acc[m][2*i2+1][half*2+0] + cbias;
                    const float o1 = acc[m][2*i2+1][half*2+1] + cbias;
                    const float cx = sel ? e0 : o0;
                    const float cy = sel ? e1 : o1;
                    const float ax = sel ? o0 : e0;
                    const float ay = sel ? o1 : e1;
                    const float rx = __shfl_xor_sync(0xffffffffu, cx, 1);
                    const float ry = __shfl_xor_sync(0xffffffffu, cy, 1);
                    const float v0 = sel ? rx : ax;
                    const float v1 = sel ? ry : ay;
                    const float v2 = sel ? ax : rx;
                    const float v3 = sel ? ay : ry;
                    asm volatile("st.global.cs.v4.f32 [%0], {%1,%2,%3,%4};"
                                 :: "l"(prow + i2 * 16 + sel * 8 + coff),
                                    "f"(v0), "f"(v1), "f"(v2), "f"(v3) : "memory");
                }
            }
        }

        if (jt < 7) {
            CP_WAIT0();
            __syncthreads();
        }
    }
}

// ---------------------------------------------------------------------------
extern "C" void kernel_launch(void* const* d_in, const int* in_sizes, int n_in,
                              void* d_out, int out_size)
{
    const float* q  = (const float*)d_in[0];
    const float* k  = (const float*)d_in[1];
    const float* W  = (const float*)d_in[2];
    const float* b  = (const float*)d_in[3];
    const float* Wd = (const float*)d_in[4];
    float* out = (float*)d_out;

    cudaFuncSetAttribute(score_mma_kernel,
                         cudaFuncAttributeMaxDynamicSharedMemorySize, SC_SMEM);

    dim3 g3(1, SV / 64, BH);
    score_mma_kernel<<<g3, 128, SC_SMEM>>>(q, k, W, b, Wd, out);
}